// round 15
// baseline (speedup 1.0000x reference)
#include <cuda_runtime.h>
#include <cuda_bf16.h>
#include <cuda_fp16.h>
#include <math.h>
#include <stdint.h>

// Problem constants
#define Bn 4
#define Nn 1025
#define Cn 768
#define Hh 12
#define DhD 64
#define BH (Bn*Hh)          // 48
#define Mtot (Bn*Nn)        // 4100
#define C3 (3*Cn)           // 2304
#define KSEL 256
#define NPAD 1088           // 17*64 padded j length

// ===========================================================================
// Scratch (static device globals — no allocation)
// ===========================================================================
__device__ float g_colsum[Bn * Nn];
__device__ float g_keep[Bn * Nn];
__device__ float g_cnt[Nn];
__device__ float2 g_stats[(size_t)BH * Nn];              // (0, 1/sumexp) per row
__device__ __half g_E[(size_t)BH * Nn * NPAD];           // exp(s) fp16 (~107MB)
__device__ __half g_xf[(size_t)Mtot * Cn];               // x fp16
__device__ __half g_wqt[(size_t)C3 * Cn];                // Wqkv^T fp16
__device__ __half g_wpt[(size_t)Cn * Cn];                // Wproj^T fp16
__device__ __half g_qf[(size_t)BH * Nn * DhD];           // Q fp16
__device__ __half g_kf[(size_t)BH * Nn * DhD];           // K fp16
__device__ __half g_vn[(size_t)BH * Nn * DhD];           // V rows fp16
__device__ __half g_vt[(size_t)BH * DhD * NPAD];         // V^T fp16
__device__ __half g_cf[(size_t)Mtot * Cn];               // ctx fp16

__device__ __forceinline__ float read_scalar_flex(const void* p) {
    int iv = *(const int*)p;
    if (iv >= 0 && iv < (1 << 24)) return (float)iv;
    return *(const float*)p;
}
__device__ __forceinline__ uint32_t smem_u32(const void* p) {
    uint32_t a;
    asm("{ .reg .u64 t; cvta.to.shared.u64 t, %1; cvt.u32.u64 %0, t; }" : "=r"(a) : "l"(p));
    return a;
}
__device__ __forceinline__ void ldsm4(uint32_t* r, uint32_t addr) {
    asm volatile("ldmatrix.sync.aligned.m8n8.x4.shared.b16 {%0,%1,%2,%3}, [%4];"
        : "=r"(r[0]), "=r"(r[1]), "=r"(r[2]), "=r"(r[3]) : "r"(addr));
}
__device__ __forceinline__ void mma16816h(float* d, const uint32_t* a, const uint32_t* b) {
    asm volatile(
        "mma.sync.aligned.m16n8k16.row.col.f32.f16.f16.f32 "
        "{%0,%1,%2,%3}, {%4,%5,%6,%7}, {%8,%9}, {%0,%1,%2,%3};"
        : "+f"(d[0]), "+f"(d[1]), "+f"(d[2]), "+f"(d[3])
        : "r"(a[0]), "r"(a[1]), "r"(a[2]), "r"(a[3]), "r"(b[0]), "r"(b[1]));
}
__device__ __forceinline__ void cp16(uint32_t dst, const void* src, bool v) {
    asm volatile("cp.async.cg.shared.global [%0], [%1], 16, %2;"
        :: "r"(dst), "l"(src), "r"(v ? 16 : 0) : "memory");
}
__device__ __forceinline__ void cp_commit() {
    asm volatile("cp.async.commit_group;" ::: "memory");
}
__device__ __forceinline__ float pairsum_h(uint32_t r) {
    __half2 h;
    *(uint32_t*)&h = r;
    float2 f = __half22float2(h);
    return f.x + f.y;
}

// ===========================================================================
// K: zero small buffers
// ===========================================================================
__global__ void zero_misc(float* colsum, float* keep, float* cnt) {
    int i = blockIdx.x * 256 + threadIdx.x;
    if (i < Bn * Nn) { colsum[i] = 0.f; keep[i] = 0.f; }
    if (i < Nn) cnt[i] = 0.f;
}

// K: fp32 -> fp16 convert (vector4)
__global__ __launch_bounds__(256) void cvt16(const float* __restrict__ s,
                                             __half* __restrict__ d, int n4) {
    int i = blockIdx.x * 256 + threadIdx.x;
    if (i >= n4) return;
    float4 v = ((const float4*)s)[i];
    __half2 a, b;
    a.x = __float2half(v.x); a.y = __float2half(v.y);
    b.x = __float2half(v.z); b.y = __float2half(v.w);
    ((__half2*)d)[2 * i]     = a;
    ((__half2*)d)[2 * i + 1] = b;
}

// K: transpose + convert:  W[K,Nc] -> T[Nc,K] fp16
__global__ __launch_bounds__(256) void tcvt(const float* __restrict__ W,
                                            __half* __restrict__ T, int K, int Nc) {
    __shared__ float tile[32][33];
    int n0 = blockIdx.x * 32, k0 = blockIdx.y * 32;
    int tx = threadIdx.x % 32, ty = threadIdx.x / 32;
    #pragma unroll
    for (int i = 0; i < 32; i += 8)
        tile[ty + i][tx] = W[(size_t)(k0 + ty + i) * Nc + n0 + tx];
    __syncthreads();
    #pragma unroll
    for (int i = 0; i < 32; i += 8)
        T[(size_t)(n0 + ty + i) * K + k0 + tx] = __float2half(tile[tx][ty + i]);
}

// K: V transpose (bh,n,d) -> (bh,d,NPAD) fp16, zero-pad j in [1025,1088)
__global__ __launch_bounds__(256) void vtrans(const __half* __restrict__ vn,
                                              __half* __restrict__ vt) {
    __shared__ __half tile[32][33];
    int z = blockIdx.z;
    int d0 = blockIdx.x * 32, n0 = blockIdx.y * 32;
    int tx = threadIdx.x % 32, ty = threadIdx.x / 32;
    #pragma unroll
    for (int i = 0; i < 32; i += 8) {
        int n = n0 + ty + i;
        tile[ty + i][tx] = (n < Nn) ? vn[((size_t)z * Nn + n) * DhD + d0 + tx]
                                    : __float2half(0.f);
    }
    __syncthreads();
    #pragma unroll
    for (int i = 0; i < 32; i += 8)
        vt[((size_t)z * DhD + d0 + ty + i) * NPAD + n0 + tx] = tile[tx][ty + i];
}

// ===========================================================================
// mm_gemm: mma.sync fp16 1-term GEMM (128x128x32, 3-stage cp.async, 2 CTA/SM)
// mode 0: QKV epilogue (q/k/v fp16 rows, coalesced)
// mode 3: OUTPROJ + bias -> fp32 out
// ===========================================================================
__global__ __launch_bounds__(256, 2) void mm_gemm(
    int mode,
    const __half* __restrict__ A, const __half* __restrict__ B,
    int M, int N, int K, int lda, int ldb,
    float* __restrict__ out, const float* __restrict__ aux,
    __half* pq, __half* pk, __half* pv)
{
    constexpr uint32_t SA = 128 * 80;       // 10240
    constexpr uint32_t SB = 128 * 80;       // 10240
    constexpr uint32_t STAGE = SA + SB;     // 20480 (x3 stages)

    extern __shared__ __align__(16) char dsm[];
    uint32_t smb = smem_u32(dsm);

    int t = threadIdx.x, wid = t >> 5, lane = t & 31;
    int warp_m = wid & 1, warp_n = wid >> 1;
    int row0 = blockIdx.y * 128, col0 = blockIdx.x * 128;

    float acc[4][4][4];
    #pragma unroll
    for (int i = 0; i < 4; i++)
        #pragma unroll
        for (int j = 0; j < 4; j++)
            #pragma unroll
            for (int c = 0; c < 4; c++) acc[i][j][c] = 0.f;

    uint32_t aRow = (uint32_t)(warp_m * 64 + (lane & 15));
    uint32_t aColB = (uint32_t)((lane >> 4) * 16);
    uint32_t bRow = (uint32_t)(warp_n * 32 + ((lane >> 4) << 3) + (lane & 7));
    uint32_t bColB = (uint32_t)(((lane >> 3) & 1) * 16);

    int nk = K / 32;

    auto load_stage = [&](int stg, int kc) {
        int k0 = kc * 32;
        uint32_t base = smb + (uint32_t)stg * STAGE;
        #pragma unroll
        for (int s = 0; s < 2; s++) {
            int l = t + s * 256;
            int r = l >> 2, u = l & 3;
            int gr = row0 + r;
            bool v = gr < M;
            cp16(base + (uint32_t)(r * 80 + u * 16),
                 A + (size_t)(v ? gr : 0) * lda + k0 + u * 8, v);
        }
        #pragma unroll
        for (int s = 0; s < 2; s++) {
            int l = t + s * 256;
            int r = l >> 2, u = l & 3;
            int gn = col0 + r;
            bool v = gn < N;
            cp16(base + SA + (uint32_t)(r * 80 + u * 16),
                 B + (size_t)(v ? gn : 0) * ldb + k0 + u * 8, v);
        }
        cp_commit();
    };

    load_stage(0, 0);
    load_stage(1, 1);

    for (int kc = 0; kc < nk; kc++) {
        if (kc + 2 < nk) {
            load_stage((kc + 2) % 3, kc + 2);
            asm volatile("cp.async.wait_group 2;" ::: "memory");
        } else if (kc + 1 < nk) {
            asm volatile("cp.async.wait_group 1;" ::: "memory");
        } else {
            asm volatile("cp.async.wait_group 0;" ::: "memory");
        }
        __syncthreads();

        uint32_t base = smb + (uint32_t)(kc % 3) * STAGE;

        #pragma unroll
        for (int ks = 0; ks < 2; ks++) {
            uint32_t af[4][4];
            uint32_t bf[4][2];
            #pragma unroll
            for (int i = 0; i < 4; i++) {
                uint32_t off = (aRow + i * 16) * 80 + aColB + ks * 32;
                ldsm4(af[i], base + off);
            }
            #pragma unroll
            for (int jp = 0; jp < 2; jp++) {
                uint32_t off = (bRow + jp * 16) * 80 + bColB + ks * 32;
                uint32_t th[4];
                ldsm4(th, base + SA + off);
                bf[jp * 2][0] = th[0]; bf[jp * 2][1] = th[1];
                bf[jp * 2 + 1][0] = th[2]; bf[jp * 2 + 1][1] = th[3];
            }
            #pragma unroll
            for (int i = 0; i < 4; i++)
                #pragma unroll
                for (int j = 0; j < 4; j++)
                    mma16816h(acc[i][j], af[i], bf[j]);
        }
        __syncthreads();
    }

    int mb = row0 + warp_m * 64 + (lane >> 2);
    int nb = col0 + warp_n * 32 + ((lane & 3) << 1);

    #pragma unroll
    for (int i = 0; i < 4; i++) {
        #pragma unroll
        for (int rr = 0; rr < 2; rr++) {
            int gm = mb + i * 16 + rr * 8;
            if (gm >= M) continue;
            int b_of = 0, n_of = 0;
            if (mode == 0) { b_of = gm / Nn; n_of = gm - b_of * Nn; }
            #pragma unroll
            for (int j = 0; j < 4; j++) {
                #pragma unroll
                for (int cc = 0; cc < 2; cc++) {
                    int gn = nb + j * 8 + cc;
                    float val = acc[i][j][rr * 2 + cc];
                    if (mode == 0) {
                        int sec = gn / Cn, rem = gn - sec * Cn;
                        int h = rem >> 6, d = rem & 63;
                        int bh = b_of * Hh + h;
                        size_t idx = ((size_t)bh * Nn + n_of) * DhD + d;
                        if (sec == 0)      pq[idx] = __float2half(val);
                        else if (sec == 1) pk[idx] = __float2half(val);
                        else               pv[idx] = __float2half(val);
                    } else {
                        if (gn < N)
                            out[(size_t)gm * Cn + gn] = val + aux[gn];
                    }
                }
            }
        }
    }
}

// ===========================================================================
// attn_fused: single pass, 64-row i-tiles, fp16 Q/K 1-term MMA, 3-stage K ring.
//   scores -> E=exp(s) fp16 -> rowsum -> stats=(0, 1/S).
// ===========================================================================
__global__ __launch_bounds__(256, 2) void attn_fused(
    const __half* __restrict__ qf, const __half* __restrict__ kf,
    __half* __restrict__ Eg, float2* __restrict__ stats)
{
    constexpr uint32_t CHUNK = 64 * 80;           // 5120
    constexpr uint32_t QSZ = 2 * CHUNK;           // 10240
    constexpr uint32_t KCH = 64 * 80;             // 5120
    constexpr uint32_t KSTG = 2 * KCH;            // 10240 (x3 stages)
    constexpr int NJT = 17;

    extern __shared__ __align__(16) char dsm[];
    __shared__ float sm_s[4][64];
    uint32_t smb = smem_u32(dsm);

    int t = threadIdx.x, wid = t >> 5, lane = t & 31;
    int warp_m = wid & 1, warp_n = wid >> 1;
    int it = blockIdx.x, z = blockIdx.y;
    int row0 = it * 64;

    const __half* Q = qf + (size_t)z * Nn * DhD;
    const __half* Kf = kf + (size_t)z * Nn * DhD;
    __half* E = Eg + (size_t)z * Nn * NPAD;

    {
        int r = t >> 2, u = t & 3;
        int gm = row0 + r;
        bool v = gm < Nn;
        #pragma unroll
        for (int c = 0; c < 2; c++) {
            size_t off = (size_t)(v ? gm : 0) * DhD + c * 32 + u * 8;
            cp16(smb + c * CHUNK + (uint32_t)(r * 80 + u * 16), Q + off, v);
        }
    }
    cp_commit();

    auto loadK = [&](int stg, int jt) {
        int j0 = jt * 64;
        uint32_t base = smb + QSZ + (uint32_t)stg * KSTG;
        int r = t >> 2, u = t & 3;
        int gn = j0 + r;
        bool v = gn < Nn;
        #pragma unroll
        for (int c = 0; c < 2; c++) {
            const __half* src = Kf + (size_t)(v ? gn : 0) * DhD + c * 32 + u * 8;
            cp16(base + (uint32_t)c * KCH + (uint32_t)(r * 80 + u * 16), src, v);
        }
        cp_commit();
    };

    loadK(0, 0);
    loadK(1, 1);

    uint32_t aRow = (uint32_t)(warp_m * 32 + (lane & 15));
    uint32_t aColB = (uint32_t)((lane >> 4) * 16);
    uint32_t bRow = (uint32_t)(warp_n * 16 + ((lane >> 4) << 3) + (lane & 7));
    uint32_t bColB = (uint32_t)(((lane >> 3) & 1) * 16);

    int nbr = warp_n * 16 + ((lane & 3) << 1);
    int mbl = warp_m * 32 + (lane >> 2);

    float sacc[2][2] = {{0.f, 0.f}, {0.f, 0.f}};
    float acc[2][2][4];

    for (int jt = 0; jt < NJT; jt++) {
        int col0 = jt * 64;

        if (jt + 2 < NJT) {
            loadK((jt + 2) % 3, jt + 2);
            asm volatile("cp.async.wait_group 2;" ::: "memory");
        } else if (jt + 1 < NJT) {
            asm volatile("cp.async.wait_group 1;" ::: "memory");
        } else {
            asm volatile("cp.async.wait_group 0;" ::: "memory");
        }
        __syncthreads();

        #pragma unroll
        for (int i = 0; i < 2; i++)
            #pragma unroll
            for (int j = 0; j < 2; j++)
                #pragma unroll
                for (int c = 0; c < 4; c++) acc[i][j][c] = 0.f;

        uint32_t kb = smb + QSZ + (uint32_t)(jt % 3) * KSTG;
        #pragma unroll
        for (int c = 0; c < 2; c++) {
            #pragma unroll
            for (int ks = 0; ks < 2; ks++) {
                uint32_t af[2][4];
                uint32_t bf[2][2];
                #pragma unroll
                for (int i = 0; i < 2; i++) {
                    uint32_t off = (aRow + i * 16) * 80 + aColB + ks * 32;
                    ldsm4(af[i], smb + c * CHUNK + off);
                }
                {
                    uint32_t off = bRow * 80 + bColB + ks * 32;
                    uint32_t th[4];
                    ldsm4(th, kb + (uint32_t)c * KCH + off);
                    bf[0][0] = th[0]; bf[0][1] = th[1];
                    bf[1][0] = th[2]; bf[1][1] = th[3];
                }
                #pragma unroll
                for (int i = 0; i < 2; i++)
                    #pragma unroll
                    for (int j = 0; j < 2; j++)
                        mma16816h(acc[i][j], af[i], bf[j]);
            }
        }

        // exp + rowsum + E store (fp16)
        #pragma unroll
        for (int i = 0; i < 2; i++) {
            #pragma unroll
            for (int rr = 0; rr < 2; rr++) {
                int gm = row0 + mbl + i * 16 + rr * 8;
                if (gm >= Nn) continue;
                #pragma unroll
                for (int j = 0; j < 2; j++) {
                    int gn0 = col0 + nbr + j * 8;
                    float e0 = 0.f, e1 = 0.f;
                    if (gn0 < Nn)     e0 = __expf(acc[i][j][rr * 2 + 0] * 0.125f);
                    if (gn0 + 1 < Nn) e1 = __expf(acc[i][j][rr * 2 + 1] * 0.125f);
                    sacc[i][rr] += e0 + e1;
                    __half2 hv;
                    hv.x = __float2half(e0);
                    hv.y = __float2half(e1);
                    *(__half2*)(E + (size_t)gm * NPAD + gn0) = hv;
                }
            }
        }
        __syncthreads();
    }

    #pragma unroll
    for (int i = 0; i < 2; i++)
        #pragma unroll
        for (int rr = 0; rr < 2; rr++) {
            float s = sacc[i][rr];
            s += __shfl_xor_sync(~0u, s, 1);
            s += __shfl_xor_sync(~0u, s, 2);
            if ((lane & 3) == 0) {
                int lr = warp_m * 32 + i * 16 + rr * 8 + (lane >> 2);
                sm_s[warp_n][lr] = s;
            }
        }
    __syncthreads();
    if (t < 64) {
        int gm = row0 + t;
        if (gm < Nn) {
            float S = sm_s[0][t] + sm_s[1][t] + sm_s[2][t] + sm_s[3][t];
            stats[(size_t)z * Nn + gm] = make_float2(0.f, 1.f / S);
        }
    }
}

// ===========================================================================
// colsum3: colsum[b][j] = sum over (h,i) of E[z][i][j] * inv[z][i]
// ===========================================================================
__global__ __launch_bounds__(256) void colsum3(
    const __half* __restrict__ Eg, const float2* __restrict__ stats,
    float* __restrict__ colsum)
{
    int j = blockIdx.x * 256 + threadIdx.x;
    if (j >= Nn) return;
    int b = blockIdx.y;
    int h = blockIdx.z >> 3;
    int chunk = blockIdx.z & 7;
    int i0 = chunk * 129;
    int i1 = min(Nn, i0 + 129);
    int z = b * Hh + h;
    const __half* E = Eg + ((size_t)z * Nn + i0) * NPAD + j;
    const float2* st = stats + (size_t)z * Nn + i0;
    float a = 0.f;
    for (int i = i0; i < i1; i++) {
        a += __half2float(*E) * st->y;
        E += NPAD;
        st++;
    }
    atomicAdd(&colsum[b * Nn + j], a);
}

// ===========================================================================
// ctx_fused: masked renorm context from stored E, 3-stage ring.
//   out_row = (mask.E) @ V / (rowsum(mask.E) + 1e-8 * S_row) -> cf fp16
// ===========================================================================
__global__ __launch_bounds__(256, 2) void ctx_fused(
    const __half* __restrict__ Eg,
    const __half* __restrict__ vt,
    const float2* __restrict__ stats, const float* __restrict__ keep,
    __half* __restrict__ cf)
{
    constexpr uint32_t ECH = 64 * 80;       // 5120
    constexpr uint32_t ESZ = 2 * ECH;       // 10240
    constexpr uint32_t VCH = 64 * 80;       // 5120
    constexpr uint32_t VSZ = 2 * VCH;       // 10240
    constexpr uint32_t STG = ESZ + VSZ;     // 20480 (x3 stages)
    constexpr int NJT = 17;

    extern __shared__ __align__(16) char dsm[];
    __shared__ uint32_t sbm[2 * NJT];
    __shared__ uint32_t svm[2 * NJT];
    __shared__ float srow[64];
    uint32_t smb = smem_u32(dsm);

    int t = threadIdx.x, wid = t >> 5, lane = t & 31;
    int warp_m = wid & 3, warp_n = wid >> 2;
    int it = blockIdx.x, z = blockIdx.y;
    int row0 = it * 64;
    int b = z / Hh, h = z - b * Hh;

    const __half* E = Eg + (size_t)z * Nn * NPAD;
    const __half* Vt = vt + (size_t)z * DhD * NPAD;

    if (t < 2 * NJT) {
        uint32_t wk = 0, wv = 0;
        #pragma unroll 8
        for (int u = 0; u < 32; u++) {
            int j = t * 32 + u;
            if (j < Nn) {
                wv |= (1u << u);
                if (keep[b * Nn + j] > 0.f) wk |= (1u << u);
            }
        }
        sbm[t] = wk;
        svm[t] = wv;
    }

    int rbase = row0 + warp_m * 16 + (lane >> 2);
    bool kr[2] = {false, false};
    float eps[2] = {1.f, 1.f};
    #pragma unroll
    for (int rr = 0; rr < 2; rr++) {
        int gm = rbase + rr * 8;
        if (gm < Nn) {
            kr[rr] = keep[b * Nn + gm] > 0.f;
            eps[rr] = 1e-8f / stats[(size_t)z * Nn + gm].y;
        }
    }
    __syncthreads();

    auto load_stage = [&](int stg, int jt) {
        int j0 = jt * 64;
        uint32_t base = smb + (uint32_t)stg * STG;
        int r = t >> 2, u = t & 3;
        {
            int gm = row0 + r;
            bool v = gm < Nn;
            #pragma unroll
            for (int c = 0; c < 2; c++) {
                const __half* src = E + (size_t)(v ? gm : 0) * NPAD + j0 + c * 32 + u * 8;
                cp16(base + (uint32_t)c * ECH + (uint32_t)(r * 80 + u * 16), src, v);
            }
        }
        #pragma unroll
        for (int c = 0; c < 2; c++) {
            const __half* src = Vt + (size_t)r * NPAD + j0 + c * 32 + u * 8;
            cp16(base + ESZ + (uint32_t)c * VCH + (uint32_t)(r * 80 + u * 16), src, true);
        }
        cp_commit();
    };

    load_stage(0, 0);
    load_stage(1, 1);

    uint32_t aRow = (uint32_t)(warp_m * 16 + (lane & 15));
    uint32_t aColB = (uint32_t)((lane >> 4) * 16);
    uint32_t bRow = (uint32_t)(warp_n * 32 + ((lane >> 4) << 3) + (lane & 7));
    uint32_t bColB = (uint32_t)(((lane >> 3) & 1) * 16);
    int c2 = (lane & 3) * 2;

    float Oacc[4][4];
    #pragma unroll
    for (int j = 0; j < 4; j++)
        #pragma unroll
        for (int c = 0; c < 4; c++) Oacc[j][c] = 0.f;
    float rs[2] = {0.f, 0.f};

    for (int jt = 0; jt < NJT; jt++) {
        if (jt + 2 < NJT) {
            load_stage((jt + 2) % 3, jt + 2);
            asm volatile("cp.async.wait_group 2;" ::: "memory");
        } else if (jt + 1 < NJT) {
            asm volatile("cp.async.wait_group 1;" ::: "memory");
        } else {
            asm volatile("cp.async.wait_group 0;" ::: "memory");
        }
        __syncthreads();

        uint32_t base = smb + (uint32_t)(jt % 3) * STG;
        uint32_t bm0 = sbm[2 * jt], bm1 = sbm[2 * jt + 1];
        uint32_t vm0 = svm[2 * jt], vm1 = svm[2 * jt + 1];

        #pragma unroll
        for (int g = 0; g < 4; g++) {
            int c = g >> 1, ks = g & 1;
            uint32_t wkk = (((g < 2) ? bm0 : bm1) >> ((g & 1) * 16)) & 0xFFFFu;
            uint32_t wvv = (((g < 2) ? vm0 : vm1) >> ((g & 1) * 16)) & 0xFFFFu;
            uint32_t k0 = (((wkk >> c2) & 1u) * 0xFFFFu) | (((wkk >> (c2 + 1)) & 1u) * 0xFFFF0000u);
            uint32_t k1 = (((wkk >> (c2 + 8)) & 1u) * 0xFFFFu) | (((wkk >> (c2 + 9)) & 1u) * 0xFFFF0000u);
            uint32_t v0 = (((wvv >> c2) & 1u) * 0xFFFFu) | (((wvv >> (c2 + 1)) & 1u) * 0xFFFF0000u);
            uint32_t v1 = (((wvv >> (c2 + 8)) & 1u) * 0xFFFFu) | (((wvv >> (c2 + 9)) & 1u) * 0xFFFF0000u);

            uint32_t af[4];
            ldsm4(af, base + (uint32_t)c * ECH + aRow * 80 + aColB + (uint32_t)(ks * 32));
            af[0] &= kr[0] ? v0 : k0;
            af[1] &= kr[1] ? v0 : k0;
            af[2] &= kr[0] ? v1 : k1;
            af[3] &= kr[1] ? v1 : k1;
            if (warp_n == 0) {
                rs[0] += pairsum_h(af[0]) + pairsum_h(af[2]);
                rs[1] += pairsum_h(af[1]) + pairsum_h(af[3]);
            }
            {
                uint32_t vf[4];
                uint32_t voff = base + ESZ + (uint32_t)c * VCH;
                uint32_t off0 = bRow * 80 + bColB + (uint32_t)(ks * 32);
                ldsm4(vf, voff + off0);
                uint32_t b0[2] = {vf[0], vf[1]}, b1[2] = {vf[2], vf[3]};
                mma16816h(Oacc[0], af, b0);
                mma16816h(Oacc[1], af, b1);
                ldsm4(vf, voff + off0 + 16 * 80);
                uint32_t b2[2] = {vf[0], vf[1]}, b3[2] = {vf[2], vf[3]};
                mma16816h(Oacc[2], af, b2);
                mma16816h(Oacc[3], af, b3);
            }
        }
        __syncthreads();
    }

    if (warp_n == 0) {
        #pragma unroll
        for (int rr = 0; rr < 2; rr++) {
            float v = rs[rr];
            v += __shfl_xor_sync(~0u, v, 1);
            v += __shfl_xor_sync(~0u, v, 2);
            if ((lane & 3) == 0)
                srow[warp_m * 16 + (lane >> 2) + rr * 8] = v;
        }
    }
    __syncthreads();

    #pragma unroll
    for (int rr = 0; rr < 2; rr++) {
        int gm = rbase + rr * 8;
        if (gm >= Nn) continue;
        float inv = 1.f / (srow[gm - row0] + eps[rr]);
        #pragma unroll
        for (int jf = 0; jf < 4; jf++) {
            #pragma unroll
            for (int cc = 0; cc < 2; cc++) {
                int d = warp_n * 32 + jf * 8 + (lane & 3) * 2 + cc;
                float val = Oacc[jf][rr * 2 + cc] * inv;
                cf[((size_t)b * Nn + gm) * Cn + h * DhD + d] = __float2half(val);
            }
        }
    }
}

// ===========================================================================
// K: UCB + top-256 bitonic
// ===========================================================================
__global__ __launch_bounds__(1024) void topk_kernel(
    const float* __restrict__ colsum, const float* __restrict__ ucb_count,
    const void* counter_p, const void* ucb_p,
    float* __restrict__ keep, float* __restrict__ cnt)
{
    int b = blockIdx.x;
    int tid = threadIdx.x;
    float counter = read_scalar_flex(counter_p);
    float ucb_en = read_scalar_flex(ucb_p);
    bool prune = (ucb_en != 0.f) && (counter > 50.f);
    if (!prune) {
        for (int j = tid; j < Nn; j += 1024) keep[b * Nn + j] = 1.f;
        return;
    }
    __shared__ float sval[1024];
    __shared__ int sidx[1024];
    float logc = logf(counter + 1.f);
    float e = 0.f;
    #pragma unroll
    for (int h = 0; h < Hh; h++)
        e += sqrtf(logc / (ucb_count[h * Nn + tid + 1] + 1e-6f));
    e *= (1.0f / (float)Hh);
    float val = colsum[b * Nn + tid + 1] * (1.f / (float)(Hh * Nn)) + e;
    sval[tid] = val;
    sidx[tid] = tid;
    __syncthreads();
    for (int k = 2; k <= 1024; k <<= 1) {
        for (int j = k >> 1; j > 0; j >>= 1) {
            int ixj = tid ^ j;
            if (ixj > tid) {
                float v1 = sval[tid], v2 = sval[ixj];
                int i1 = sidx[tid], i2 = sidx[ixj];
                bool after = (v1 < v2) || (v1 == v2 && i1 > i2);
                bool desc = ((tid & k) == 0);
                if (desc ? after : !after) {
                    sval[tid] = v2; sval[ixj] = v1;
                    sidx[tid] = i2; sidx[ixj] = i1;
                }
            }
            __syncthreads();
        }
    }
    if (tid < KSEL) {
        int tok = sidx[tid] + 1;
        keep[b * Nn + tok] = 1.f;
        atomicAdd(&cnt[tok], 1.f);
    }
    if (tid == 0) keep[b * Nn + 0] = 1.f;
}

// K: score_delta[h,j] = cnt[j] / B
__global__ void score_delta_kernel(const float* __restrict__ cnt, float* __restrict__ out2) {
    int i = blockIdx.x * 256 + threadIdx.x;
    if (i >= Hh * Nn) return;
    out2[i] = cnt[i % Nn] * (1.f / (float)Bn);
}

// ===========================================================================
extern "C" void kernel_launch(void* const* d_in, const int* in_sizes, int n_in,
                              void* d_out, int out_size)
{
    const float* x     = (const float*)d_in[0];
    const float* ucb   = (const float*)d_in[1];
    const float* Wqkv  = (const float*)d_in[2];
    const float* Wproj = (const float*)d_in[3];
    const float* bproj = (const float*)d_in[4];
    const void*  cntr  = d_in[5];
    const void*  uen   = d_in[6];

    float *colsum, *keep, *cnt;
    float2* stats;
    __half *Eg, *xf, *wqt, *wpt, *qf, *kf, *vn, *vt, *cf;
    cudaGetSymbolAddress((void**)&colsum, g_colsum);
    cudaGetSymbolAddress((void**)&keep,   g_keep);
    cudaGetSymbolAddress((void**)&cnt,    g_cnt);
    cudaGetSymbolAddress((void**)&stats,  g_stats);
    cudaGetSymbolAddress((void**)&Eg,     g_E);
    cudaGetSymbolAddress((void**)&xf,     g_xf);
    cudaGetSymbolAddress((void**)&wqt,    g_wqt);
    cudaGetSymbolAddress((void**)&wpt,    g_wpt);
    cudaGetSymbolAddress((void**)&qf,     g_qf);
    cudaGetSymbolAddress((void**)&kf,     g_kf);
    cudaGetSymbolAddress((void**)&vn,     g_vn);
    cudaGetSymbolAddress((void**)&vt,     g_vt);
    cudaGetSymbolAddress((void**)&cf,     g_cf);

    const int SMEM128 = 3 * (128 * 80 + 128 * 80);        // 61440
    const int SMEMATT = 2 * 64 * 80 + 3 * (2 * 64 * 80);  // 40960
    const int SMEMCTX = 3 * (2 * 64 * 80 + 2 * 64 * 80);  // 61440
    cudaFuncSetAttribute(mm_gemm,    cudaFuncAttributeMaxDynamicSharedMemorySize, SMEM128);
    cudaFuncSetAttribute(attn_fused, cudaFuncAttributeMaxDynamicSharedMemorySize, SMEMATT);
    cudaFuncSetAttribute(ctx_fused,  cudaFuncAttributeMaxDynamicSharedMemorySize, SMEMCTX);

    const int NXE = Mtot * Cn;

    // prep (ordered so attn_fused lands in ncu's fixed -s 5 capture slot)
    cvt16<<<(NXE / 4 + 255) / 256, 256>>>(x, xf, NXE / 4);
    tcvt<<<dim3(C3 / 32, Cn / 32), 256>>>(Wqkv, wqt, Cn, C3);
    tcvt<<<dim3(Cn / 32, Cn / 32), 256>>>(Wproj, wpt, Cn, Cn);

    // 1) QKV projection (fp16 1-term)
    mm_gemm<<<dim3(C3 / 128, 33, 1), 256, SMEM128>>>(0, xf, wqt,
        Mtot, C3, Cn, Cn, Cn, nullptr, nullptr, qf, kf, vn);

    // 2) fused scores (fp16 1-term) + exp store + rowsum stats
    attn_fused<<<dim3(17, BH), 256, SMEMATT>>>(qf, kf, Eg, stats);

    // 2b) V transpose with padding (needed only by ctx)
    vtrans<<<dim3(DhD / 32, NPAD / 32, BH), 256>>>(vn, vt);

    // 2c) zero small buffers (needed before colsum/topk)
    zero_misc<<<(Bn * Nn + 255) / 256, 256>>>(colsum, keep, cnt);

    // 3) column sums from E
    colsum3<<<dim3(5, Bn, Hh * 8), 256>>>(Eg, stats, colsum);

    // 4) UCB top-k
    topk_kernel<<<Bn, 1024>>>(colsum, ucb, cntr, uen, keep, cnt);

    // 5) masked renorm context from E -> cf fp16
    ctx_fused<<<dim3(17, BH), 256, SMEMCTX>>>(Eg, vt, stats, keep, cf);

    // 6) out projection (fp16 1-term)
    mm_gemm<<<dim3(6, 33, 1), 256, SMEM128>>>(3, cf, wpt,
        Mtot, Cn, Cn, Cn, Cn, (float*)d_out, bproj,
        nullptr, nullptr, nullptr);

    // 7) score_delta
    if (out_size >= Mtot * Cn + Hh * Nn) {
        float* out2 = (float*)d_out + (size_t)Mtot * Cn;
        score_delta_kernel<<<(Hh * Nn + 255) / 256, 256>>>(cnt, out2);
    }
}

// round 16
// speedup vs baseline: 1.0765x; 1.0765x over previous
#include <cuda_runtime.h>
#include <cuda_bf16.h>
#include <cuda_fp16.h>
#include <math.h>
#include <stdint.h>

// Problem constants
#define Bn 4
#define Nn 1025
#define Cn 768
#define Hh 12
#define DhD 64
#define BH (Bn*Hh)          // 48
#define Mtot (Bn*Nn)        // 4100
#define C3 (3*Cn)           // 2304
#define KSEL 256
#define NPAD 1088           // 17*64 padded j length

// ===========================================================================
// Scratch (static device globals — no allocation)
// ===========================================================================
__device__ float g_colsum[Bn * Nn];
__device__ float g_keep[Bn * Nn];
__device__ float g_cnt[Nn];
__device__ float2 g_stats[(size_t)BH * Nn];              // (0, 1/sumexp) per row
__device__ __half g_E[(size_t)BH * Nn * NPAD];           // exp(s) fp16 (~107MB)
__device__ __half g_xf[(size_t)Mtot * Cn];               // x fp16
__device__ __half g_wqt[(size_t)C3 * Cn];                // Wqkv^T fp16
__device__ __half g_wpt[(size_t)Cn * Cn];                // Wproj^T fp16
__device__ __half g_qf[(size_t)BH * Nn * DhD];           // Q fp16
__device__ __half g_kf[(size_t)BH * Nn * DhD];           // K fp16
__device__ __half g_vn[(size_t)BH * Nn * DhD];           // V rows fp16
__device__ __half g_vt[(size_t)BH * DhD * NPAD];         // V^T fp16
__device__ __half g_cf[(size_t)Mtot * Cn];               // ctx fp16

__device__ __forceinline__ float read_scalar_flex(const void* p) {
    int iv = *(const int*)p;
    if (iv >= 0 && iv < (1 << 24)) return (float)iv;
    return *(const float*)p;
}
__device__ __forceinline__ uint32_t smem_u32(const void* p) {
    uint32_t a;
    asm("{ .reg .u64 t; cvta.to.shared.u64 t, %1; cvt.u32.u64 %0, t; }" : "=r"(a) : "l"(p));
    return a;
}
__device__ __forceinline__ void ldsm4(uint32_t* r, uint32_t addr) {
    asm volatile("ldmatrix.sync.aligned.m8n8.x4.shared.b16 {%0,%1,%2,%3}, [%4];"
        : "=r"(r[0]), "=r"(r[1]), "=r"(r[2]), "=r"(r[3]) : "r"(addr));
}
__device__ __forceinline__ void mma16816h(float* d, const uint32_t* a, const uint32_t* b) {
    asm volatile(
        "mma.sync.aligned.m16n8k16.row.col.f32.f16.f16.f32 "
        "{%0,%1,%2,%3}, {%4,%5,%6,%7}, {%8,%9}, {%0,%1,%2,%3};"
        : "+f"(d[0]), "+f"(d[1]), "+f"(d[2]), "+f"(d[3])
        : "r"(a[0]), "r"(a[1]), "r"(a[2]), "r"(a[3]), "r"(b[0]), "r"(b[1]));
}
__device__ __forceinline__ void cp16(uint32_t dst, const void* src, bool v) {
    asm volatile("cp.async.cg.shared.global [%0], [%1], 16, %2;"
        :: "r"(dst), "l"(src), "r"(v ? 16 : 0) : "memory");
}
__device__ __forceinline__ void cp_commit() {
    asm volatile("cp.async.commit_group;" ::: "memory");
}
__device__ __forceinline__ float pairsum_h(uint32_t r) {
    __half2 h;
    *(uint32_t*)&h = r;
    float2 f = __half22float2(h);
    return f.x + f.y;
}
__device__ __forceinline__ __half2 mkh2(float a, float b) {
    __half2 h;
    h.x = __float2half(a);
    h.y = __float2half(b);
    return h;
}

// ===========================================================================
// K: zero small buffers
// ===========================================================================
__global__ void zero_misc(float* colsum, float* keep, float* cnt) {
    int i = blockIdx.x * 256 + threadIdx.x;
    if (i < Bn * Nn) { colsum[i] = 0.f; keep[i] = 0.f; }
    if (i < Nn) cnt[i] = 0.f;
}

// K: fp32 -> fp16 convert (vector4)
__global__ __launch_bounds__(256) void cvt16(const float* __restrict__ s,
                                             __half* __restrict__ d, int n4) {
    int i = blockIdx.x * 256 + threadIdx.x;
    if (i >= n4) return;
    float4 v = ((const float4*)s)[i];
    ((__half2*)d)[2 * i]     = mkh2(v.x, v.y);
    ((__half2*)d)[2 * i + 1] = mkh2(v.z, v.w);
}

// K: transpose + convert:  W[K,Nc] -> T[Nc,K] fp16
__global__ __launch_bounds__(256) void tcvt(const float* __restrict__ W,
                                            __half* __restrict__ T, int K, int Nc) {
    __shared__ float tile[32][33];
    int n0 = blockIdx.x * 32, k0 = blockIdx.y * 32;
    int tx = threadIdx.x % 32, ty = threadIdx.x / 32;
    #pragma unroll
    for (int i = 0; i < 32; i += 8)
        tile[ty + i][tx] = W[(size_t)(k0 + ty + i) * Nc + n0 + tx];
    __syncthreads();
    #pragma unroll
    for (int i = 0; i < 32; i += 8)
        T[(size_t)(n0 + ty + i) * K + k0 + tx] = __float2half(tile[tx][ty + i]);
}

// K: V transpose (bh,n,d) -> (bh,d,NPAD) fp16, zero-pad j in [1025,1088)
__global__ __launch_bounds__(256) void vtrans(const __half* __restrict__ vn,
                                              __half* __restrict__ vt) {
    __shared__ __half tile[32][33];
    int z = blockIdx.z;
    int d0 = blockIdx.x * 32, n0 = blockIdx.y * 32;
    int tx = threadIdx.x % 32, ty = threadIdx.x / 32;
    #pragma unroll
    for (int i = 0; i < 32; i += 8) {
        int n = n0 + ty + i;
        tile[ty + i][tx] = (n < Nn) ? vn[((size_t)z * Nn + n) * DhD + d0 + tx]
                                    : __float2half(0.f);
    }
    __syncthreads();
    #pragma unroll
    for (int i = 0; i < 32; i += 8)
        vt[((size_t)z * DhD + d0 + ty + i) * NPAD + n0 + tx] = tile[tx][ty + i];
}

// ===========================================================================
// mm_gemm: mma.sync fp16 1-term GEMM (128x128x32, 3-stage, single-sync loop)
// mode 0: QKV epilogue (q/k/v fp16 rows, half2 stores)
// mode 3: OUTPROJ + bias -> fp32 out (float2 stores)
// ===========================================================================
__global__ __launch_bounds__(256, 2) void mm_gemm(
    int mode,
    const __half* __restrict__ A, const __half* __restrict__ B,
    int M, int N, int K, int lda, int ldb,
    float* __restrict__ out, const float* __restrict__ aux,
    __half* pq, __half* pk, __half* pv)
{
    constexpr uint32_t SA = 128 * 80;       // 10240
    constexpr uint32_t SB = 128 * 80;       // 10240
    constexpr uint32_t STAGE = SA + SB;     // 20480 (x3 stages)

    extern __shared__ __align__(16) char dsm[];
    uint32_t smb = smem_u32(dsm);

    int t = threadIdx.x, wid = t >> 5, lane = t & 31;
    int warp_m = wid & 1, warp_n = wid >> 1;
    int row0 = blockIdx.y * 128, col0 = blockIdx.x * 128;

    float acc[4][4][4];
    #pragma unroll
    for (int i = 0; i < 4; i++)
        #pragma unroll
        for (int j = 0; j < 4; j++)
            #pragma unroll
            for (int c = 0; c < 4; c++) acc[i][j][c] = 0.f;

    uint32_t aRow = (uint32_t)(warp_m * 64 + (lane & 15));
    uint32_t aColB = (uint32_t)((lane >> 4) * 16);
    uint32_t bRow = (uint32_t)(warp_n * 32 + ((lane >> 4) << 3) + (lane & 7));
    uint32_t bColB = (uint32_t)(((lane >> 3) & 1) * 16);

    int nk = K / 32;

    auto load_stage = [&](int stg, int kc) {
        int k0 = kc * 32;
        uint32_t base = smb + (uint32_t)stg * STAGE;
        #pragma unroll
        for (int s = 0; s < 2; s++) {
            int l = t + s * 256;
            int r = l >> 2, u = l & 3;
            int gr = row0 + r;
            bool v = gr < M;
            cp16(base + (uint32_t)(r * 80 + u * 16),
                 A + (size_t)(v ? gr : 0) * lda + k0 + u * 8, v);
        }
        #pragma unroll
        for (int s = 0; s < 2; s++) {
            int l = t + s * 256;
            int r = l >> 2, u = l & 3;
            int gn = col0 + r;
            bool v = gn < N;
            cp16(base + SA + (uint32_t)(r * 80 + u * 16),
                 B + (size_t)(v ? gn : 0) * ldb + k0 + u * 8, v);
        }
        cp_commit();
    };

    load_stage(0, 0);
    load_stage(1, 1);

    for (int kc = 0; kc < nk; kc++) {
        if (kc + 1 < nk) {
            asm volatile("cp.async.wait_group 1;" ::: "memory");
        } else {
            asm volatile("cp.async.wait_group 0;" ::: "memory");
        }
        __syncthreads();
        if (kc + 2 < nk) load_stage((kc + 2) % 3, kc + 2);

        uint32_t base = smb + (uint32_t)(kc % 3) * STAGE;

        #pragma unroll
        for (int ks = 0; ks < 2; ks++) {
            uint32_t af[4][4];
            uint32_t bf[4][2];
            #pragma unroll
            for (int i = 0; i < 4; i++) {
                uint32_t off = (aRow + i * 16) * 80 + aColB + ks * 32;
                ldsm4(af[i], base + off);
            }
            #pragma unroll
            for (int jp = 0; jp < 2; jp++) {
                uint32_t off = (bRow + jp * 16) * 80 + bColB + ks * 32;
                uint32_t th[4];
                ldsm4(th, base + SA + off);
                bf[jp * 2][0] = th[0]; bf[jp * 2][1] = th[1];
                bf[jp * 2 + 1][0] = th[2]; bf[jp * 2 + 1][1] = th[3];
            }
            #pragma unroll
            for (int i = 0; i < 4; i++)
                #pragma unroll
                for (int j = 0; j < 4; j++)
                    mma16816h(acc[i][j], af[i], bf[j]);
        }
    }

    int mb = row0 + warp_m * 64 + (lane >> 2);
    int nb = col0 + warp_n * 32 + ((lane & 3) << 1);

    #pragma unroll
    for (int i = 0; i < 4; i++) {
        #pragma unroll
        for (int rr = 0; rr < 2; rr++) {
            int gm = mb + i * 16 + rr * 8;
            if (gm >= M) continue;
            int b_of = 0, n_of = 0;
            if (mode == 0) { b_of = gm / Nn; n_of = gm - b_of * Nn; }
            #pragma unroll
            for (int j = 0; j < 4; j++) {
                int gn = nb + j * 8;        // even; pair (gn, gn+1)
                float v0 = acc[i][j][rr * 2 + 0];
                float v1 = acc[i][j][rr * 2 + 1];
                if (mode == 0) {
                    int sec = gn / Cn, rem = gn - sec * Cn;
                    int h = rem >> 6, d = rem & 63;     // d even, d+1 same head
                    int bh = b_of * Hh + h;
                    size_t idx = ((size_t)bh * Nn + n_of) * DhD + d;
                    __half2 hv = mkh2(v0, v1);
                    if (sec == 0)      *(__half2*)(pq + idx) = hv;
                    else if (sec == 1) *(__half2*)(pk + idx) = hv;
                    else               *(__half2*)(pv + idx) = hv;
                } else {
                    if (gn < N)
                        *(float2*)(out + (size_t)gm * Cn + gn) =
                            make_float2(v0 + aux[gn], v1 + aux[gn + 1]);
                }
            }
        }
    }
}

// ===========================================================================
// attn_fused: single pass, 64-row i-tiles, fp16 1-term MMA, 3-stage K ring,
//   single-sync loop. scores -> E=exp(s) fp16 -> rowsum -> stats=(0, 1/S).
// ===========================================================================
__global__ __launch_bounds__(256, 2) void attn_fused(
    const __half* __restrict__ qf, const __half* __restrict__ kf,
    __half* __restrict__ Eg, float2* __restrict__ stats)
{
    constexpr uint32_t CHUNK = 64 * 80;           // 5120
    constexpr uint32_t QSZ = 2 * CHUNK;           // 10240
    constexpr uint32_t KCH = 64 * 80;             // 5120
    constexpr uint32_t KSTG = 2 * KCH;            // 10240 (x3 stages)
    constexpr int NJT = 17;

    extern __shared__ __align__(16) char dsm[];
    __shared__ float sm_s[4][64];
    uint32_t smb = smem_u32(dsm);

    int t = threadIdx.x, wid = t >> 5, lane = t & 31;
    int warp_m = wid & 1, warp_n = wid >> 1;
    int it = blockIdx.x, z = blockIdx.y;
    int row0 = it * 64;

    const __half* Q = qf + (size_t)z * Nn * DhD;
    const __half* Kf = kf + (size_t)z * Nn * DhD;
    __half* E = Eg + (size_t)z * Nn * NPAD;

    {
        int r = t >> 2, u = t & 3;
        int gm = row0 + r;
        bool v = gm < Nn;
        #pragma unroll
        for (int c = 0; c < 2; c++) {
            size_t off = (size_t)(v ? gm : 0) * DhD + c * 32 + u * 8;
            cp16(smb + c * CHUNK + (uint32_t)(r * 80 + u * 16), Q + off, v);
        }
    }
    cp_commit();

    auto loadK = [&](int stg, int jt) {
        int j0 = jt * 64;
        uint32_t base = smb + QSZ + (uint32_t)stg * KSTG;
        int r = t >> 2, u = t & 3;
        int gn = j0 + r;
        bool v = gn < Nn;
        #pragma unroll
        for (int c = 0; c < 2; c++) {
            const __half* src = Kf + (size_t)(v ? gn : 0) * DhD + c * 32 + u * 8;
            cp16(base + (uint32_t)c * KCH + (uint32_t)(r * 80 + u * 16), src, v);
        }
        cp_commit();
    };

    loadK(0, 0);
    loadK(1, 1);

    uint32_t aRow = (uint32_t)(warp_m * 32 + (lane & 15));
    uint32_t aColB = (uint32_t)((lane >> 4) * 16);
    uint32_t bRow = (uint32_t)(warp_n * 16 + ((lane >> 4) << 3) + (lane & 7));
    uint32_t bColB = (uint32_t)(((lane >> 3) & 1) * 16);

    int nbr = warp_n * 16 + ((lane & 3) << 1);
    int mbl = warp_m * 32 + (lane >> 2);

    float sacc[2][2] = {{0.f, 0.f}, {0.f, 0.f}};
    float acc[2][2][4];

    for (int jt = 0; jt < NJT; jt++) {
        int col0 = jt * 64;

        if (jt + 1 < NJT) {
            asm volatile("cp.async.wait_group 1;" ::: "memory");
        } else {
            asm volatile("cp.async.wait_group 0;" ::: "memory");
        }
        __syncthreads();
        if (jt + 2 < NJT) loadK((jt + 2) % 3, jt + 2);

        #pragma unroll
        for (int i = 0; i < 2; i++)
            #pragma unroll
            for (int j = 0; j < 2; j++)
                #pragma unroll
                for (int c = 0; c < 4; c++) acc[i][j][c] = 0.f;

        uint32_t kb = smb + QSZ + (uint32_t)(jt % 3) * KSTG;
        #pragma unroll
        for (int c = 0; c < 2; c++) {
            #pragma unroll
            for (int ks = 0; ks < 2; ks++) {
                uint32_t af[2][4];
                uint32_t bf[2][2];
                #pragma unroll
                for (int i = 0; i < 2; i++) {
                    uint32_t off = (aRow + i * 16) * 80 + aColB + ks * 32;
                    ldsm4(af[i], smb + c * CHUNK + off);
                }
                {
                    uint32_t off = bRow * 80 + bColB + ks * 32;
                    uint32_t th[4];
                    ldsm4(th, kb + (uint32_t)c * KCH + off);
                    bf[0][0] = th[0]; bf[0][1] = th[1];
                    bf[1][0] = th[2]; bf[1][1] = th[3];
                }
                #pragma unroll
                for (int i = 0; i < 2; i++)
                    #pragma unroll
                    for (int j = 0; j < 2; j++)
                        mma16816h(acc[i][j], af[i], bf[j]);
            }
        }

        // exp + rowsum + E store (fp16)
        #pragma unroll
        for (int i = 0; i < 2; i++) {
            #pragma unroll
            for (int rr = 0; rr < 2; rr++) {
                int gm = row0 + mbl + i * 16 + rr * 8;
                if (gm >= Nn) continue;
                #pragma unroll
                for (int j = 0; j < 2; j++) {
                    int gn0 = col0 + nbr + j * 8;
                    float e0 = 0.f, e1 = 0.f;
                    if (gn0 < Nn)     e0 = __expf(acc[i][j][rr * 2 + 0] * 0.125f);
                    if (gn0 + 1 < Nn) e1 = __expf(acc[i][j][rr * 2 + 1] * 0.125f);
                    sacc[i][rr] += e0 + e1;
                    *(__half2*)(E + (size_t)gm * NPAD + gn0) = mkh2(e0, e1);
                }
            }
        }
    }

    #pragma unroll
    for (int i = 0; i < 2; i++)
        #pragma unroll
        for (int rr = 0; rr < 2; rr++) {
            float s = sacc[i][rr];
            s += __shfl_xor_sync(~0u, s, 1);
            s += __shfl_xor_sync(~0u, s, 2);
            if ((lane & 3) == 0) {
                int lr = warp_m * 32 + i * 16 + rr * 8 + (lane >> 2);
                sm_s[warp_n][lr] = s;
            }
        }
    __syncthreads();
    if (t < 64) {
        int gm = row0 + t;
        if (gm < Nn) {
            float S = sm_s[0][t] + sm_s[1][t] + sm_s[2][t] + sm_s[3][t];
            stats[(size_t)z * Nn + gm] = make_float2(0.f, 1.f / S);
        }
    }
}

// ===========================================================================
// colsum3: colsum[b][j] = sum over (h,i) of E[z][i][j] * inv[z][i]
// ===========================================================================
__global__ __launch_bounds__(256) void colsum3(
    const __half* __restrict__ Eg, const float2* __restrict__ stats,
    float* __restrict__ colsum)
{
    int j = blockIdx.x * 256 + threadIdx.x;
    if (j >= Nn) return;
    int b = blockIdx.y;
    int h = blockIdx.z >> 3;
    int chunk = blockIdx.z & 7;
    int i0 = chunk * 129;
    int i1 = min(Nn, i0 + 129);
    int z = b * Hh + h;
    const __half* E = Eg + ((size_t)z * Nn + i0) * NPAD + j;
    const float2* st = stats + (size_t)z * Nn + i0;
    float a = 0.f;
    for (int i = i0; i < i1; i++) {
        a += __half2float(*E) * st->y;
        E += NPAD;
        st++;
    }
    atomicAdd(&colsum[b * Nn + j], a);
}

// ===========================================================================
// ctx_fused: masked renorm context from stored E, 3-stage ring, single-sync.
//   out_row = (mask.E) @ V / (rowsum(mask.E) + 1e-8 * S_row) -> cf fp16
// ===========================================================================
__global__ __launch_bounds__(256, 2) void ctx_fused(
    const __half* __restrict__ Eg,
    const __half* __restrict__ vt,
    const float2* __restrict__ stats, const float* __restrict__ keep,
    __half* __restrict__ cf)
{
    constexpr uint32_t ECH = 64 * 80;       // 5120
    constexpr uint32_t ESZ = 2 * ECH;       // 10240
    constexpr uint32_t VCH = 64 * 80;       // 5120
    constexpr uint32_t VSZ = 2 * VCH;       // 10240
    constexpr uint32_t STG = ESZ + VSZ;     // 20480 (x3 stages)
    constexpr int NJT = 17;

    extern __shared__ __align__(16) char dsm[];
    __shared__ uint32_t sbm[2 * NJT];
    __shared__ uint32_t svm[2 * NJT];
    __shared__ float srow[64];
    uint32_t smb = smem_u32(dsm);

    int t = threadIdx.x, wid = t >> 5, lane = t & 31;
    int warp_m = wid & 3, warp_n = wid >> 2;
    int it = blockIdx.x, z = blockIdx.y;
    int row0 = it * 64;
    int b = z / Hh, h = z - b * Hh;

    const __half* E = Eg + (size_t)z * Nn * NPAD;
    const __half* Vt = vt + (size_t)z * DhD * NPAD;

    if (t < 2 * NJT) {
        uint32_t wk = 0, wv = 0;
        #pragma unroll 8
        for (int u = 0; u < 32; u++) {
            int j = t * 32 + u;
            if (j < Nn) {
                wv |= (1u << u);
                if (keep[b * Nn + j] > 0.f) wk |= (1u << u);
            }
        }
        sbm[t] = wk;
        svm[t] = wv;
    }

    int rbase = row0 + warp_m * 16 + (lane >> 2);
    bool kr[2] = {false, false};
    float eps[2] = {1.f, 1.f};
    #pragma unroll
    for (int rr = 0; rr < 2; rr++) {
        int gm = rbase + rr * 8;
        if (gm < Nn) {
            kr[rr] = keep[b * Nn + gm] > 0.f;
            eps[rr] = 1e-8f / stats[(size_t)z * Nn + gm].y;
        }
    }
    __syncthreads();

    auto load_stage = [&](int stg, int jt) {
        int j0 = jt * 64;
        uint32_t base = smb + (uint32_t)stg * STG;
        int r = t >> 2, u = t & 3;
        {
            int gm = row0 + r;
            bool v = gm < Nn;
            #pragma unroll
            for (int c = 0; c < 2; c++) {
                const __half* src = E + (size_t)(v ? gm : 0) * NPAD + j0 + c * 32 + u * 8;
                cp16(base + (uint32_t)c * ECH + (uint32_t)(r * 80 + u * 16), src, v);
            }
        }
        #pragma unroll
        for (int c = 0; c < 2; c++) {
            const __half* src = Vt + (size_t)r * NPAD + j0 + c * 32 + u * 8;
            cp16(base + ESZ + (uint32_t)c * VCH + (uint32_t)(r * 80 + u * 16), src, true);
        }
        cp_commit();
    };

    load_stage(0, 0);
    load_stage(1, 1);

    uint32_t aRow = (uint32_t)(warp_m * 16 + (lane & 15));
    uint32_t aColB = (uint32_t)((lane >> 4) * 16);
    uint32_t bRow = (uint32_t)(warp_n * 32 + ((lane >> 4) << 3) + (lane & 7));
    uint32_t bColB = (uint32_t)(((lane >> 3) & 1) * 16);
    int c2 = (lane & 3) * 2;

    float Oacc[4][4];
    #pragma unroll
    for (int j = 0; j < 4; j++)
        #pragma unroll
        for (int c = 0; c < 4; c++) Oacc[j][c] = 0.f;
    float rs[2] = {0.f, 0.f};

    for (int jt = 0; jt < NJT; jt++) {
        if (jt + 1 < NJT) {
            asm volatile("cp.async.wait_group 1;" ::: "memory");
        } else {
            asm volatile("cp.async.wait_group 0;" ::: "memory");
        }
        __syncthreads();
        if (jt + 2 < NJT) load_stage((jt + 2) % 3, jt + 2);

        uint32_t base = smb + (uint32_t)(jt % 3) * STG;
        uint32_t bm0 = sbm[2 * jt], bm1 = sbm[2 * jt + 1];
        uint32_t vm0 = svm[2 * jt], vm1 = svm[2 * jt + 1];

        #pragma unroll
        for (int g = 0; g < 4; g++) {
            int c = g >> 1, ks = g & 1;
            uint32_t wkk = (((g < 2) ? bm0 : bm1) >> ((g & 1) * 16)) & 0xFFFFu;
            uint32_t wvv = (((g < 2) ? vm0 : vm1) >> ((g & 1) * 16)) & 0xFFFFu;
            uint32_t k0 = (((wkk >> c2) & 1u) * 0xFFFFu) | (((wkk >> (c2 + 1)) & 1u) * 0xFFFF0000u);
            uint32_t k1 = (((wkk >> (c2 + 8)) & 1u) * 0xFFFFu) | (((wkk >> (c2 + 9)) & 1u) * 0xFFFF0000u);
            uint32_t v0 = (((wvv >> c2) & 1u) * 0xFFFFu) | (((wvv >> (c2 + 1)) & 1u) * 0xFFFF0000u);
            uint32_t v1 = (((wvv >> (c2 + 8)) & 1u) * 0xFFFFu) | (((wvv >> (c2 + 9)) & 1u) * 0xFFFF0000u);

            uint32_t af[4];
            ldsm4(af, base + (uint32_t)c * ECH + aRow * 80 + aColB + (uint32_t)(ks * 32));
            af[0] &= kr[0] ? v0 : k0;
            af[1] &= kr[1] ? v0 : k0;
            af[2] &= kr[0] ? v1 : k1;
            af[3] &= kr[1] ? v1 : k1;
            if (warp_n == 0) {
                rs[0] += pairsum_h(af[0]) + pairsum_h(af[2]);
                rs[1] += pairsum_h(af[1]) + pairsum_h(af[3]);
            }
            {
                uint32_t vf[4];
                uint32_t voff = base + ESZ + (uint32_t)c * VCH;
                uint32_t off0 = bRow * 80 + bColB + (uint32_t)(ks * 32);
                ldsm4(vf, voff + off0);
                uint32_t b0[2] = {vf[0], vf[1]}, b1[2] = {vf[2], vf[3]};
                mma16816h(Oacc[0], af, b0);
                mma16816h(Oacc[1], af, b1);
                ldsm4(vf, voff + off0 + 16 * 80);
                uint32_t b2[2] = {vf[0], vf[1]}, b3[2] = {vf[2], vf[3]};
                mma16816h(Oacc[2], af, b2);
                mma16816h(Oacc[3], af, b3);
            }
        }
    }

    if (warp_n == 0) {
        #pragma unroll
        for (int rr = 0; rr < 2; rr++) {
            float v = rs[rr];
            v += __shfl_xor_sync(~0u, v, 1);
            v += __shfl_xor_sync(~0u, v, 2);
            if ((lane & 3) == 0)
                srow[warp_m * 16 + (lane >> 2) + rr * 8] = v;
        }
    }
    __syncthreads();

    #pragma unroll
    for (int rr = 0; rr < 2; rr++) {
        int gm = rbase + rr * 8;
        if (gm >= Nn) continue;
        float inv = 1.f / (srow[gm - row0] + eps[rr]);
        #pragma unroll
        for (int jf = 0; jf < 4; jf++) {
            int d = warp_n * 32 + jf * 8 + (lane & 3) * 2;   // even pair
            float v0 = Oacc[jf][rr * 2 + 0] * inv;
            float v1 = Oacc[jf][rr * 2 + 1] * inv;
            *(__half2*)(cf + ((size_t)b * Nn + gm) * Cn + h * DhD + d) = mkh2(v0, v1);
        }
    }
}

// ===========================================================================
// K: UCB + top-256 bitonic
// ===========================================================================
__global__ __launch_bounds__(1024) void topk_kernel(
    const float* __restrict__ colsum, const float* __restrict__ ucb_count,
    const void* counter_p, const void* ucb_p,
    float* __restrict__ keep, float* __restrict__ cnt)
{
    int b = blockIdx.x;
    int tid = threadIdx.x;
    float counter = read_scalar_flex(counter_p);
    float ucb_en = read_scalar_flex(ucb_p);
    bool prune = (ucb_en != 0.f) && (counter > 50.f);
    if (!prune) {
        for (int j = tid; j < Nn; j += 1024) keep[b * Nn + j] = 1.f;
        return;
    }
    __shared__ float sval[1024];
    __shared__ int sidx[1024];
    float logc = logf(counter + 1.f);
    float e = 0.f;
    #pragma unroll
    for (int h = 0; h < Hh; h++)
        e += sqrtf(logc / (ucb_count[h * Nn + tid + 1] + 1e-6f));
    e *= (1.0f / (float)Hh);
    float val = colsum[b * Nn + tid + 1] * (1.f / (float)(Hh * Nn)) + e;
    sval[tid] = val;
    sidx[tid] = tid;
    __syncthreads();
    for (int k = 2; k <= 1024; k <<= 1) {
        for (int j = k >> 1; j > 0; j >>= 1) {
            int ixj = tid ^ j;
            if (ixj > tid) {
                float v1 = sval[tid], v2 = sval[ixj];
                int i1 = sidx[tid], i2 = sidx[ixj];
                bool after = (v1 < v2) || (v1 == v2 && i1 > i2);
                bool desc = ((tid & k) == 0);
                if (desc ? after : !after) {
                    sval[tid] = v2; sval[ixj] = v1;
                    sidx[tid] = i2; sidx[ixj] = i1;
                }
            }
            __syncthreads();
        }
    }
    if (tid < KSEL) {
        int tok = sidx[tid] + 1;
        keep[b * Nn + tok] = 1.f;
        atomicAdd(&cnt[tok], 1.f);
    }
    if (tid == 0) keep[b * Nn + 0] = 1.f;
}

// K: score_delta[h,j] = cnt[j] / B
__global__ void score_delta_kernel(const float* __restrict__ cnt, float* __restrict__ out2) {
    int i = blockIdx.x * 256 + threadIdx.x;
    if (i >= Hh * Nn) return;
    out2[i] = cnt[i % Nn] * (1.f / (float)Bn);
}

// ===========================================================================
extern "C" void kernel_launch(void* const* d_in, const int* in_sizes, int n_in,
                              void* d_out, int out_size)
{
    const float* x     = (const float*)d_in[0];
    const float* ucb   = (const float*)d_in[1];
    const float* Wqkv  = (const float*)d_in[2];
    const float* Wproj = (const float*)d_in[3];
    const float* bproj = (const float*)d_in[4];
    const void*  cntr  = d_in[5];
    const void*  uen   = d_in[6];

    float *colsum, *keep, *cnt;
    float2* stats;
    __half *Eg, *xf, *wqt, *wpt, *qf, *kf, *vn, *vt, *cf;
    cudaGetSymbolAddress((void**)&colsum, g_colsum);
    cudaGetSymbolAddress((void**)&keep,   g_keep);
    cudaGetSymbolAddress((void**)&cnt,    g_cnt);
    cudaGetSymbolAddress((void**)&stats,  g_stats);
    cudaGetSymbolAddress((void**)&Eg,     g_E);
    cudaGetSymbolAddress((void**)&xf,     g_xf);
    cudaGetSymbolAddress((void**)&wqt,    g_wqt);
    cudaGetSymbolAddress((void**)&wpt,    g_wpt);
    cudaGetSymbolAddress((void**)&qf,     g_qf);
    cudaGetSymbolAddress((void**)&kf,     g_kf);
    cudaGetSymbolAddress((void**)&vn,     g_vn);
    cudaGetSymbolAddress((void**)&vt,     g_vt);
    cudaGetSymbolAddress((void**)&cf,     g_cf);

    const int SMEM128 = 3 * (128 * 80 + 128 * 80);        // 61440
    const int SMEMATT = 2 * 64 * 80 + 3 * (2 * 64 * 80);  // 40960
    const int SMEMCTX = 3 * (2 * 64 * 80 + 2 * 64 * 80);  // 61440
    cudaFuncSetAttribute(mm_gemm,    cudaFuncAttributeMaxDynamicSharedMemorySize, SMEM128);
    cudaFuncSetAttribute(attn_fused, cudaFuncAttributeMaxDynamicSharedMemorySize, SMEMATT);
    cudaFuncSetAttribute(ctx_fused,  cudaFuncAttributeMaxDynamicSharedMemorySize, SMEMCTX);

    const int NXE = Mtot * Cn;

    // prep
    cvt16<<<(NXE / 4 + 255) / 256, 256>>>(x, xf, NXE / 4);
    tcvt<<<dim3(C3 / 32, Cn / 32), 256>>>(Wqkv, wqt, Cn, C3);
    tcvt<<<dim3(Cn / 32, Cn / 32), 256>>>(Wproj, wpt, Cn, Cn);

    // 1) QKV projection (fp16 1-term)
    mm_gemm<<<dim3(C3 / 128, 33, 1), 256, SMEM128>>>(0, xf, wqt,
        Mtot, C3, Cn, Cn, Cn, nullptr, nullptr, qf, kf, vn);

    // 2) fused scores (fp16 1-term) + exp store + rowsum stats
    attn_fused<<<dim3(17, BH), 256, SMEMATT>>>(qf, kf, Eg, stats);

    // 2b) V transpose with padding (needed only by ctx)
    vtrans<<<dim3(DhD / 32, NPAD / 32, BH), 256>>>(vn, vt);

    // 2c) zero small buffers (needed before colsum/topk)
    zero_misc<<<(Bn * Nn + 255) / 256, 256>>>(colsum, keep, cnt);

    // 3) column sums from E
    colsum3<<<dim3(5, Bn, Hh * 8), 256>>>(Eg, stats, colsum);

    // 4) UCB top-k
    topk_kernel<<<Bn, 1024>>>(colsum, ucb, cntr, uen, keep, cnt);

    // 5) masked renorm context from E -> cf fp16
    ctx_fused<<<dim3(17, BH), 256, SMEMCTX>>>(Eg, vt, stats, keep, cf);

    // 6) out projection (fp16 1-term)
    mm_gemm<<<dim3(6, 33, 1), 256, SMEM128>>>(3, cf, wpt,
        Mtot, Cn, Cn, Cn, Cn, (float*)d_out, bproj,
        nullptr, nullptr, nullptr);

    // 7) score_delta
    if (out_size >= Mtot * Cn + Hh * Nn) {
        float* out2 = (float*)d_out + (size_t)Mtot * Cn;
        score_delta_kernel<<<(Hh * Nn + 255) / 256, 256>>>(cnt, out2);
    }
}

// round 17
// speedup vs baseline: 1.1237x; 1.0438x over previous
#include <cuda_runtime.h>
#include <cuda_bf16.h>
#include <cuda_fp16.h>
#include <math.h>
#include <stdint.h>

// Problem constants
#define Bn 4
#define Nn 1025
#define Cn 768
#define Hh 12
#define DhD 64
#define BH (Bn*Hh)          // 48
#define Mtot (Bn*Nn)        // 4100
#define C3 (3*Cn)           // 2304
#define KSEL 256
#define NPAD 1088           // 17*64 padded j length

// ===========================================================================
// Scratch (static device globals — no allocation)
// ===========================================================================
__device__ float g_colsum[Bn * Nn];
__device__ float g_keep[Bn * Nn];
__device__ float g_cnt[Nn];
__device__ float2 g_stats[(size_t)BH * Nn];              // (0, 1/sumexp) per row
__device__ __half g_E[(size_t)BH * Nn * NPAD];           // exp(s) fp16 (~107MB)
__device__ __half g_xf[(size_t)Mtot * Cn];               // x fp16
__device__ __half g_wqt[(size_t)C3 * Cn];                // Wqkv^T fp16
__device__ __half g_wpt[(size_t)Cn * Cn];                // Wproj^T fp16
__device__ __half g_qf[(size_t)BH * Nn * DhD];           // Q fp16
__device__ __half g_kf[(size_t)BH * Nn * DhD];           // K fp16
__device__ __half g_vn[(size_t)BH * Nn * DhD];           // V rows fp16
__device__ __half g_vt[(size_t)BH * DhD * NPAD];         // V^T fp16
__device__ __half g_cf[(size_t)Mtot * Cn];               // ctx fp16

__device__ __forceinline__ float read_scalar_flex(const void* p) {
    int iv = *(const int*)p;
    if (iv >= 0 && iv < (1 << 24)) return (float)iv;
    return *(const float*)p;
}
__device__ __forceinline__ uint32_t smem_u32(const void* p) {
    uint32_t a;
    asm("{ .reg .u64 t; cvta.to.shared.u64 t, %1; cvt.u32.u64 %0, t; }" : "=r"(a) : "l"(p));
    return a;
}
__device__ __forceinline__ void ldsm4(uint32_t* r, uint32_t addr) {
    asm volatile("ldmatrix.sync.aligned.m8n8.x4.shared.b16 {%0,%1,%2,%3}, [%4];"
        : "=r"(r[0]), "=r"(r[1]), "=r"(r[2]), "=r"(r[3]) : "r"(addr));
}
__device__ __forceinline__ void mma16816h(float* d, const uint32_t* a, const uint32_t* b) {
    asm volatile(
        "mma.sync.aligned.m16n8k16.row.col.f32.f16.f16.f32 "
        "{%0,%1,%2,%3}, {%4,%5,%6,%7}, {%8,%9}, {%0,%1,%2,%3};"
        : "+f"(d[0]), "+f"(d[1]), "+f"(d[2]), "+f"(d[3])
        : "r"(a[0]), "r"(a[1]), "r"(a[2]), "r"(a[3]), "r"(b[0]), "r"(b[1]));
}
__device__ __forceinline__ void cp16(uint32_t dst, const void* src, bool v) {
    asm volatile("cp.async.cg.shared.global [%0], [%1], 16, %2;"
        :: "r"(dst), "l"(src), "r"(v ? 16 : 0) : "memory");
}
__device__ __forceinline__ void cp_commit() {
    asm volatile("cp.async.commit_group;" ::: "memory");
}
__device__ __forceinline__ float pairsum_h(uint32_t r) {
    __half2 h;
    *(uint32_t*)&h = r;
    float2 f = __half22float2(h);
    return f.x + f.y;
}
__device__ __forceinline__ __half2 mkh2(float a, float b) {
    __half2 h;
    h.x = __float2half(a);
    h.y = __float2half(b);
    return h;
}

// ===========================================================================
// K: zero small buffers
// ===========================================================================
__global__ void zero_misc(float* colsum, float* keep, float* cnt) {
    int i = blockIdx.x * 256 + threadIdx.x;
    if (i < Bn * Nn) { colsum[i] = 0.f; keep[i] = 0.f; }
    if (i < Nn) cnt[i] = 0.f;
}

// K: fp32 -> fp16 convert (vector4)
__global__ __launch_bounds__(256) void cvt16(const float* __restrict__ s,
                                             __half* __restrict__ d, int n4) {
    int i = blockIdx.x * 256 + threadIdx.x;
    if (i >= n4) return;
    float4 v = ((const float4*)s)[i];
    ((__half2*)d)[2 * i]     = mkh2(v.x, v.y);
    ((__half2*)d)[2 * i + 1] = mkh2(v.z, v.w);
}

// K: transpose + convert:  W[K,Nc] -> T[Nc,K] fp16
__global__ __launch_bounds__(256) void tcvt(const float* __restrict__ W,
                                            __half* __restrict__ T, int K, int Nc) {
    __shared__ float tile[32][33];
    int n0 = blockIdx.x * 32, k0 = blockIdx.y * 32;
    int tx = threadIdx.x % 32, ty = threadIdx.x / 32;
    #pragma unroll
    for (int i = 0; i < 32; i += 8)
        tile[ty + i][tx] = W[(size_t)(k0 + ty + i) * Nc + n0 + tx];
    __syncthreads();
    #pragma unroll
    for (int i = 0; i < 32; i += 8)
        T[(size_t)(n0 + ty + i) * K + k0 + tx] = __float2half(tile[tx][ty + i]);
}

// K: V transpose (bh,n,d) -> (bh,d,NPAD) fp16, zero-pad j in [1025,1088)
__global__ __launch_bounds__(256) void vtrans(const __half* __restrict__ vn,
                                              __half* __restrict__ vt) {
    __shared__ __half tile[32][33];
    int z = blockIdx.z;
    int d0 = blockIdx.x * 32, n0 = blockIdx.y * 32;
    int tx = threadIdx.x % 32, ty = threadIdx.x / 32;
    #pragma unroll
    for (int i = 0; i < 32; i += 8) {
        int n = n0 + ty + i;
        tile[ty + i][tx] = (n < Nn) ? vn[((size_t)z * Nn + n) * DhD + d0 + tx]
                                    : __float2half(0.f);
    }
    __syncthreads();
    #pragma unroll
    for (int i = 0; i < 32; i += 8)
        vt[((size_t)z * DhD + d0 + ty + i) * NPAD + n0 + tx] = tile[tx][ty + i];
}

// ===========================================================================
// mm_gemm: mma.sync fp16 1-term GEMM (128x128x32, 3-stage, single-sync loop)
// mode 0: QKV epilogue (q/k/v fp16 rows, half2 stores)
// mode 3: OUTPROJ + bias -> fp32 out (float2 stores)
// ===========================================================================
__global__ __launch_bounds__(256, 2) void mm_gemm(
    int mode,
    const __half* __restrict__ A, const __half* __restrict__ B,
    int M, int N, int K, int lda, int ldb,
    float* __restrict__ out, const float* __restrict__ aux,
    __half* pq, __half* pk, __half* pv)
{
    constexpr uint32_t SA = 128 * 80;       // 10240
    constexpr uint32_t SB = 128 * 80;       // 10240
    constexpr uint32_t STAGE = SA + SB;     // 20480 (x3 stages)

    extern __shared__ __align__(16) char dsm[];
    uint32_t smb = smem_u32(dsm);

    int t = threadIdx.x, wid = t >> 5, lane = t & 31;
    int warp_m = wid & 1, warp_n = wid >> 1;
    int row0 = blockIdx.y * 128, col0 = blockIdx.x * 128;

    float acc[4][4][4];
    #pragma unroll
    for (int i = 0; i < 4; i++)
        #pragma unroll
        for (int j = 0; j < 4; j++)
            #pragma unroll
            for (int c = 0; c < 4; c++) acc[i][j][c] = 0.f;

    uint32_t aRow = (uint32_t)(warp_m * 64 + (lane & 15));
    uint32_t aColB = (uint32_t)((lane >> 4) * 16);
    uint32_t bRow = (uint32_t)(warp_n * 32 + ((lane >> 4) << 3) + (lane & 7));
    uint32_t bColB = (uint32_t)(((lane >> 3) & 1) * 16);

    int nk = K / 32;

    auto load_stage = [&](int stg, int kc) {
        int k0 = kc * 32;
        uint32_t base = smb + (uint32_t)stg * STAGE;
        #pragma unroll
        for (int s = 0; s < 2; s++) {
            int l = t + s * 256;
            int r = l >> 2, u = l & 3;
            int gr = row0 + r;
            bool v = gr < M;
            cp16(base + (uint32_t)(r * 80 + u * 16),
                 A + (size_t)(v ? gr : 0) * lda + k0 + u * 8, v);
        }
        #pragma unroll
        for (int s = 0; s < 2; s++) {
            int l = t + s * 256;
            int r = l >> 2, u = l & 3;
            int gn = col0 + r;
            bool v = gn < N;
            cp16(base + SA + (uint32_t)(r * 80 + u * 16),
                 B + (size_t)(v ? gn : 0) * ldb + k0 + u * 8, v);
        }
        cp_commit();
    };

    load_stage(0, 0);
    load_stage(1, 1);

    for (int kc = 0; kc < nk; kc++) {
        if (kc + 1 < nk) {
            asm volatile("cp.async.wait_group 1;" ::: "memory");
        } else {
            asm volatile("cp.async.wait_group 0;" ::: "memory");
        }
        __syncthreads();
        if (kc + 2 < nk) load_stage((kc + 2) % 3, kc + 2);

        uint32_t base = smb + (uint32_t)(kc % 3) * STAGE;

        #pragma unroll
        for (int ks = 0; ks < 2; ks++) {
            uint32_t af[4][4];
            uint32_t bf[4][2];
            #pragma unroll
            for (int i = 0; i < 4; i++) {
                uint32_t off = (aRow + i * 16) * 80 + aColB + ks * 32;
                ldsm4(af[i], base + off);
            }
            #pragma unroll
            for (int jp = 0; jp < 2; jp++) {
                uint32_t off = (bRow + jp * 16) * 80 + bColB + ks * 32;
                uint32_t th[4];
                ldsm4(th, base + SA + off);
                bf[jp * 2][0] = th[0]; bf[jp * 2][1] = th[1];
                bf[jp * 2 + 1][0] = th[2]; bf[jp * 2 + 1][1] = th[3];
            }
            #pragma unroll
            for (int i = 0; i < 4; i++)
                #pragma unroll
                for (int j = 0; j < 4; j++)
                    mma16816h(acc[i][j], af[i], bf[j]);
        }
    }

    int mb = row0 + warp_m * 64 + (lane >> 2);
    int nb = col0 + warp_n * 32 + ((lane & 3) << 1);

    #pragma unroll
    for (int i = 0; i < 4; i++) {
        #pragma unroll
        for (int rr = 0; rr < 2; rr++) {
            int gm = mb + i * 16 + rr * 8;
            if (gm >= M) continue;
            int b_of = 0, n_of = 0;
            if (mode == 0) { b_of = gm / Nn; n_of = gm - b_of * Nn; }
            #pragma unroll
            for (int j = 0; j < 4; j++) {
                int gn = nb + j * 8;        // even; pair (gn, gn+1)
                float v0 = acc[i][j][rr * 2 + 0];
                float v1 = acc[i][j][rr * 2 + 1];
                if (mode == 0) {
                    int sec = gn / Cn, rem = gn - sec * Cn;
                    int h = rem >> 6, d = rem & 63;
                    int bh = b_of * Hh + h;
                    size_t idx = ((size_t)bh * Nn + n_of) * DhD + d;
                    __half2 hv = mkh2(v0, v1);
                    if (sec == 0)      *(__half2*)(pq + idx) = hv;
                    else if (sec == 1) *(__half2*)(pk + idx) = hv;
                    else               *(__half2*)(pv + idx) = hv;
                } else {
                    if (gn < N)
                        *(float2*)(out + (size_t)gm * Cn + gn) =
                            make_float2(v0 + aux[gn], v1 + aux[gn + 1]);
                }
            }
        }
    }
}

// ===========================================================================
// attn_fused: single pass, 64-row i-tiles, j-tile 128 (warp tile 32x32),
//   fp16 1-term MMA, 3-stage K ring, single-sync loop.
//   scores -> E=exp(s) fp16 -> rowsum -> stats=(0, 1/S).
// ===========================================================================
__global__ __launch_bounds__(256, 2) void attn_fused(
    const __half* __restrict__ qf, const __half* __restrict__ kf,
    __half* __restrict__ Eg, float2* __restrict__ stats)
{
    constexpr uint32_t CHUNK = 64 * 80;           // Q chunk 5120
    constexpr uint32_t QSZ = 2 * CHUNK;           // 10240
    constexpr uint32_t KCH = 128 * 80;            // K chunk (128 j x 32 d) = 10240
    constexpr uint32_t KSTG = 2 * KCH;            // 20480 (x3 stages)
    constexpr int NJT = 9;                        // 9 * 128 = 1152 >= 1025

    extern __shared__ __align__(16) char dsm[];
    __shared__ float sm_s[4][64];
    uint32_t smb = smem_u32(dsm);

    int t = threadIdx.x, wid = t >> 5, lane = t & 31;
    int warp_m = wid & 1, warp_n = wid >> 1;
    int it = blockIdx.x, z = blockIdx.y;
    int row0 = it * 64;

    const __half* Q = qf + (size_t)z * Nn * DhD;
    const __half* Kf = kf + (size_t)z * Nn * DhD;
    __half* E = Eg + (size_t)z * Nn * NPAD;

    // Q tile (64 x 64) fp16 -> smem
    {
        int r = t >> 2, u = t & 3;
        int gm = row0 + r;
        bool v = gm < Nn;
        #pragma unroll
        for (int c = 0; c < 2; c++) {
            size_t off = (size_t)(v ? gm : 0) * DhD + c * 32 + u * 8;
            cp16(smb + c * CHUNK + (uint32_t)(r * 80 + u * 16), Q + off, v);
        }
    }
    cp_commit();

    auto loadK = [&](int stg, int jt) {
        int j0 = jt * 128;
        uint32_t base = smb + QSZ + (uint32_t)stg * KSTG;
        #pragma unroll
        for (int c = 0; c < 2; c++) {
            #pragma unroll
            for (int s = 0; s < 2; s++) {
                int l = t + s * 256;
                int r = l >> 2, u = l & 3;     // 128 rows x 4 chunks
                int gn = j0 + r;
                bool v = gn < Nn;
                const __half* src = Kf + (size_t)(v ? gn : 0) * DhD + c * 32 + u * 8;
                cp16(base + (uint32_t)c * KCH + (uint32_t)(r * 80 + u * 16), src, v);
            }
        }
        cp_commit();
    };

    loadK(0, 0);
    loadK(1, 1);

    uint32_t aRow = (uint32_t)(warp_m * 32 + (lane & 15));
    uint32_t aColB = (uint32_t)((lane >> 4) * 16);
    uint32_t bRow = (uint32_t)(warp_n * 32 + ((lane >> 4) << 3) + (lane & 7));
    uint32_t bColB = (uint32_t)(((lane >> 3) & 1) * 16);

    int nbr = warp_n * 32 + ((lane & 3) << 1);
    int mbl = warp_m * 32 + (lane >> 2);

    float sacc[2][2] = {{0.f, 0.f}, {0.f, 0.f}};
    float acc[2][4][4];

    for (int jt = 0; jt < NJT; jt++) {
        int col0 = jt * 128;

        if (jt + 1 < NJT) {
            asm volatile("cp.async.wait_group 1;" ::: "memory");
        } else {
            asm volatile("cp.async.wait_group 0;" ::: "memory");
        }
        __syncthreads();
        if (jt + 2 < NJT) loadK((jt + 2) % 3, jt + 2);

        #pragma unroll
        for (int i = 0; i < 2; i++)
            #pragma unroll
            for (int j = 0; j < 4; j++)
                #pragma unroll
                for (int c = 0; c < 4; c++) acc[i][j][c] = 0.f;

        uint32_t kb = smb + QSZ + (uint32_t)(jt % 3) * KSTG;
        #pragma unroll
        for (int c = 0; c < 2; c++) {
            #pragma unroll
            for (int ks = 0; ks < 2; ks++) {
                uint32_t af[2][4];
                uint32_t bf[4][2];
                #pragma unroll
                for (int i = 0; i < 2; i++) {
                    uint32_t off = (aRow + i * 16) * 80 + aColB + ks * 32;
                    ldsm4(af[i], smb + c * CHUNK + off);
                }
                #pragma unroll
                for (int jp = 0; jp < 2; jp++) {
                    uint32_t off = (bRow + jp * 16) * 80 + bColB + ks * 32;
                    uint32_t th[4];
                    ldsm4(th, kb + (uint32_t)c * KCH + off);
                    bf[jp * 2][0] = th[0]; bf[jp * 2][1] = th[1];
                    bf[jp * 2 + 1][0] = th[2]; bf[jp * 2 + 1][1] = th[3];
                }
                #pragma unroll
                for (int i = 0; i < 2; i++)
                    #pragma unroll
                    for (int j = 0; j < 4; j++)
                        mma16816h(acc[i][j], af[i], bf[j]);
            }
        }

        // exp + rowsum + E store (fp16); stores guarded to stay within NPAD
        #pragma unroll
        for (int i = 0; i < 2; i++) {
            #pragma unroll
            for (int rr = 0; rr < 2; rr++) {
                int gm = row0 + mbl + i * 16 + rr * 8;
                if (gm >= Nn) continue;
                #pragma unroll
                for (int j = 0; j < 4; j++) {
                    int gn0 = col0 + nbr + j * 8;
                    float e0 = 0.f, e1 = 0.f;
                    if (gn0 < Nn)     e0 = __expf(acc[i][j][rr * 2 + 0] * 0.125f);
                    if (gn0 + 1 < Nn) e1 = __expf(acc[i][j][rr * 2 + 1] * 0.125f);
                    sacc[i][rr] += e0 + e1;
                    if (gn0 + 1 < NPAD)
                        *(__half2*)(E + (size_t)gm * NPAD + gn0) = mkh2(e0, e1);
                }
            }
        }
    }

    #pragma unroll
    for (int i = 0; i < 2; i++)
        #pragma unroll
        for (int rr = 0; rr < 2; rr++) {
            float s = sacc[i][rr];
            s += __shfl_xor_sync(~0u, s, 1);
            s += __shfl_xor_sync(~0u, s, 2);
            if ((lane & 3) == 0) {
                int lr = warp_m * 32 + i * 16 + rr * 8 + (lane >> 2);
                sm_s[warp_n][lr] = s;
            }
        }
    __syncthreads();
    if (t < 64) {
        int gm = row0 + t;
        if (gm < Nn) {
            float S = sm_s[0][t] + sm_s[1][t] + sm_s[2][t] + sm_s[3][t];
            stats[(size_t)z * Nn + gm] = make_float2(0.f, 1.f / S);
        }
    }
}

// ===========================================================================
// colsum3: colsum[b][j] = sum over (h,i) of E[z][i][j] * inv[z][i]
//   half2 pair loads (j0, j0+1)
// ===========================================================================
__global__ __launch_bounds__(256) void colsum3(
    const __half* __restrict__ Eg, const float2* __restrict__ stats,
    float* __restrict__ colsum)
{
    int j0 = (blockIdx.x * 256 + threadIdx.x) * 2;
    if (j0 >= Nn) return;
    int b = blockIdx.y;
    int h = blockIdx.z >> 3;
    int chunk = blockIdx.z & 7;
    int i0 = chunk * 129;
    int i1 = min(Nn, i0 + 129);
    int z = b * Hh + h;
    const __half* E = Eg + ((size_t)z * Nn + i0) * NPAD + j0;
    const float2* st = stats + (size_t)z * Nn + i0;
    float a0 = 0.f, a1 = 0.f;
    for (int i = i0; i < i1; i++) {
        __half2 v = *(const __half2*)E;
        float2 f = __half22float2(v);
        a0 += f.x * st->y;
        a1 += f.y * st->y;
        E += NPAD;
        st++;
    }
    atomicAdd(&colsum[b * Nn + j0], a0);
    if (j0 + 1 < Nn) atomicAdd(&colsum[b * Nn + j0 + 1], a1);
}

// ===========================================================================
// ctx_fused: masked renorm context from stored E, 3-stage ring, single-sync.
//   out_row = (mask.E) @ V / (rowsum(mask.E) + 1e-8 * S_row) -> cf fp16
// ===========================================================================
__global__ __launch_bounds__(256, 2) void ctx_fused(
    const __half* __restrict__ Eg,
    const __half* __restrict__ vt,
    const float2* __restrict__ stats, const float* __restrict__ keep,
    __half* __restrict__ cf)
{
    constexpr uint32_t ECH = 64 * 80;       // 5120
    constexpr uint32_t ESZ = 2 * ECH;       // 10240
    constexpr uint32_t VCH = 64 * 80;       // 5120
    constexpr uint32_t VSZ = 2 * VCH;       // 10240
    constexpr uint32_t STG = ESZ + VSZ;     // 20480 (x3 stages)
    constexpr int NJT = 17;

    extern __shared__ __align__(16) char dsm[];
    __shared__ uint32_t sbm[2 * NJT];
    __shared__ uint32_t svm[2 * NJT];
    __shared__ float srow[64];
    uint32_t smb = smem_u32(dsm);

    int t = threadIdx.x, wid = t >> 5, lane = t & 31;
    int warp_m = wid & 3, warp_n = wid >> 2;
    int it = blockIdx.x, z = blockIdx.y;
    int row0 = it * 64;
    int b = z / Hh, h = z - b * Hh;

    const __half* E = Eg + (size_t)z * Nn * NPAD;
    const __half* Vt = vt + (size_t)z * DhD * NPAD;

    if (t < 2 * NJT) {
        uint32_t wk = 0, wv = 0;
        #pragma unroll 8
        for (int u = 0; u < 32; u++) {
            int j = t * 32 + u;
            if (j < Nn) {
                wv |= (1u << u);
                if (keep[b * Nn + j] > 0.f) wk |= (1u << u);
            }
        }
        sbm[t] = wk;
        svm[t] = wv;
    }

    int rbase = row0 + warp_m * 16 + (lane >> 2);
    bool kr[2] = {false, false};
    float eps[2] = {1.f, 1.f};
    #pragma unroll
    for (int rr = 0; rr < 2; rr++) {
        int gm = rbase + rr * 8;
        if (gm < Nn) {
            kr[rr] = keep[b * Nn + gm] > 0.f;
            eps[rr] = 1e-8f / stats[(size_t)z * Nn + gm].y;
        }
    }
    __syncthreads();

    auto load_stage = [&](int stg, int jt) {
        int j0 = jt * 64;
        uint32_t base = smb + (uint32_t)stg * STG;
        int r = t >> 2, u = t & 3;
        {
            int gm = row0 + r;
            bool v = gm < Nn;
            #pragma unroll
            for (int c = 0; c < 2; c++) {
                const __half* src = E + (size_t)(v ? gm : 0) * NPAD + j0 + c * 32 + u * 8;
                cp16(base + (uint32_t)c * ECH + (uint32_t)(r * 80 + u * 16), src, v);
            }
        }
        #pragma unroll
        for (int c = 0; c < 2; c++) {
            const __half* src = Vt + (size_t)r * NPAD + j0 + c * 32 + u * 8;
            cp16(base + ESZ + (uint32_t)c * VCH + (uint32_t)(r * 80 + u * 16), src, true);
        }
        cp_commit();
    };

    load_stage(0, 0);
    load_stage(1, 1);

    uint32_t aRow = (uint32_t)(warp_m * 16 + (lane & 15));
    uint32_t aColB = (uint32_t)((lane >> 4) * 16);
    uint32_t bRow = (uint32_t)(warp_n * 32 + ((lane >> 4) << 3) + (lane & 7));
    uint32_t bColB = (uint32_t)(((lane >> 3) & 1) * 16);
    int c2 = (lane & 3) * 2;

    float Oacc[4][4];
    #pragma unroll
    for (int j = 0; j < 4; j++)
        #pragma unroll
        for (int c = 0; c < 4; c++) Oacc[j][c] = 0.f;
    float rs[2] = {0.f, 0.f};

    for (int jt = 0; jt < NJT; jt++) {
        if (jt + 1 < NJT) {
            asm volatile("cp.async.wait_group 1;" ::: "memory");
        } else {
            asm volatile("cp.async.wait_group 0;" ::: "memory");
        }
        __syncthreads();
        if (jt + 2 < NJT) load_stage((jt + 2) % 3, jt + 2);

        uint32_t base = smb + (uint32_t)(jt % 3) * STG;
        uint32_t bm0 = sbm[2 * jt], bm1 = sbm[2 * jt + 1];
        uint32_t vm0 = svm[2 * jt], vm1 = svm[2 * jt + 1];

        #pragma unroll
        for (int g = 0; g < 4; g++) {
            int c = g >> 1, ks = g & 1;
            uint32_t wkk = (((g < 2) ? bm0 : bm1) >> ((g & 1) * 16)) & 0xFFFFu;
            uint32_t wvv = (((g < 2) ? vm0 : vm1) >> ((g & 1) * 16)) & 0xFFFFu;
            uint32_t k0 = (((wkk >> c2) & 1u) * 0xFFFFu) | (((wkk >> (c2 + 1)) & 1u) * 0xFFFF0000u);
            uint32_t k1 = (((wkk >> (c2 + 8)) & 1u) * 0xFFFFu) | (((wkk >> (c2 + 9)) & 1u) * 0xFFFF0000u);
            uint32_t v0 = (((wvv >> c2) & 1u) * 0xFFFFu) | (((wvv >> (c2 + 1)) & 1u) * 0xFFFF0000u);
            uint32_t v1 = (((wvv >> (c2 + 8)) & 1u) * 0xFFFFu) | (((wvv >> (c2 + 9)) & 1u) * 0xFFFF0000u);

            uint32_t af[4];
            ldsm4(af, base + (uint32_t)c * ECH + aRow * 80 + aColB + (uint32_t)(ks * 32));
            af[0] &= kr[0] ? v0 : k0;
            af[1] &= kr[1] ? v0 : k0;
            af[2] &= kr[0] ? v1 : k1;
            af[3] &= kr[1] ? v1 : k1;
            if (warp_n == 0) {
                rs[0] += pairsum_h(af[0]) + pairsum_h(af[2]);
                rs[1] += pairsum_h(af[1]) + pairsum_h(af[3]);
            }
            {
                uint32_t vf[4];
                uint32_t voff = base + ESZ + (uint32_t)c * VCH;
                uint32_t off0 = bRow * 80 + bColB + (uint32_t)(ks * 32);
                ldsm4(vf, voff + off0);
                uint32_t b0[2] = {vf[0], vf[1]}, b1[2] = {vf[2], vf[3]};
                mma16816h(Oacc[0], af, b0);
                mma16816h(Oacc[1], af, b1);
                ldsm4(vf, voff + off0 + 16 * 80);
                uint32_t b2[2] = {vf[0], vf[1]}, b3[2] = {vf[2], vf[3]};
                mma16816h(Oacc[2], af, b2);
                mma16816h(Oacc[3], af, b3);
            }
        }
    }

    if (warp_n == 0) {
        #pragma unroll
        for (int rr = 0; rr < 2; rr++) {
            float v = rs[rr];
            v += __shfl_xor_sync(~0u, v, 1);
            v += __shfl_xor_sync(~0u, v, 2);
            if ((lane & 3) == 0)
                srow[warp_m * 16 + (lane >> 2) + rr * 8] = v;
        }
    }
    __syncthreads();

    #pragma unroll
    for (int rr = 0; rr < 2; rr++) {
        int gm = rbase + rr * 8;
        if (gm >= Nn) continue;
        float inv = 1.f / (srow[gm - row0] + eps[rr]);
        #pragma unroll
        for (int jf = 0; jf < 4; jf++) {
            int d = warp_n * 32 + jf * 8 + (lane & 3) * 2;   // even pair
            float v0 = Oacc[jf][rr * 2 + 0] * inv;
            float v1 = Oacc[jf][rr * 2 + 1] * inv;
            *(__half2*)(cf + ((size_t)b * Nn + gm) * Cn + h * DhD + d) = mkh2(v0, v1);
        }
    }
}

// ===========================================================================
// K: UCB + top-256 bitonic
// ===========================================================================
__global__ __launch_bounds__(1024) void topk_kernel(
    const float* __restrict__ colsum, const float* __restrict__ ucb_count,
    const void* counter_p, const void* ucb_p,
    float* __restrict__ keep, float* __restrict__ cnt)
{
    int b = blockIdx.x;
    int tid = threadIdx.x;
    float counter = read_scalar_flex(counter_p);
    float ucb_en = read_scalar_flex(ucb_p);
    bool prune = (ucb_en != 0.f) && (counter > 50.f);
    if (!prune) {
        for (int j = tid; j < Nn; j += 1024) keep[b * Nn + j] = 1.f;
        return;
    }
    __shared__ float sval[1024];
    __shared__ int sidx[1024];
    float logc = logf(counter + 1.f);
    float e = 0.f;
    #pragma unroll
    for (int h = 0; h < Hh; h++)
        e += sqrtf(logc / (ucb_count[h * Nn + tid + 1] + 1e-6f));
    e *= (1.0f / (float)Hh);
    float val = colsum[b * Nn + tid + 1] * (1.f / (float)(Hh * Nn)) + e;
    sval[tid] = val;
    sidx[tid] = tid;
    __syncthreads();
    for (int k = 2; k <= 1024; k <<= 1) {
        for (int j = k >> 1; j > 0; j >>= 1) {
            int ixj = tid ^ j;
            if (ixj > tid) {
                float v1 = sval[tid], v2 = sval[ixj];
                int i1 = sidx[tid], i2 = sidx[ixj];
                bool after = (v1 < v2) || (v1 == v2 && i1 > i2);
                bool desc = ((tid & k) == 0);
                if (desc ? after : !after) {
                    sval[tid] = v2; sval[ixj] = v1;
                    sidx[tid] = i2; sidx[ixj] = i1;
                }
            }
            __syncthreads();
        }
    }
    if (tid < KSEL) {
        int tok = sidx[tid] + 1;
        keep[b * Nn + tok] = 1.f;
        atomicAdd(&cnt[tok], 1.f);
    }
    if (tid == 0) keep[b * Nn + 0] = 1.f;
}

// K: score_delta[h,j] = cnt[j] / B
__global__ void score_delta_kernel(const float* __restrict__ cnt, float* __restrict__ out2) {
    int i = blockIdx.x * 256 + threadIdx.x;
    if (i >= Hh * Nn) return;
    out2[i] = cnt[i % Nn] * (1.f / (float)Bn);
}

// ===========================================================================
extern "C" void kernel_launch(void* const* d_in, const int* in_sizes, int n_in,
                              void* d_out, int out_size)
{
    const float* x     = (const float*)d_in[0];
    const float* ucb   = (const float*)d_in[1];
    const float* Wqkv  = (const float*)d_in[2];
    const float* Wproj = (const float*)d_in[3];
    const float* bproj = (const float*)d_in[4];
    const void*  cntr  = d_in[5];
    const void*  uen   = d_in[6];

    float *colsum, *keep, *cnt;
    float2* stats;
    __half *Eg, *xf, *wqt, *wpt, *qf, *kf, *vn, *vt, *cf;
    cudaGetSymbolAddress((void**)&colsum, g_colsum);
    cudaGetSymbolAddress((void**)&keep,   g_keep);
    cudaGetSymbolAddress((void**)&cnt,    g_cnt);
    cudaGetSymbolAddress((void**)&stats,  g_stats);
    cudaGetSymbolAddress((void**)&Eg,     g_E);
    cudaGetSymbolAddress((void**)&xf,     g_xf);
    cudaGetSymbolAddress((void**)&wqt,    g_wqt);
    cudaGetSymbolAddress((void**)&wpt,    g_wpt);
    cudaGetSymbolAddress((void**)&qf,     g_qf);
    cudaGetSymbolAddress((void**)&kf,     g_kf);
    cudaGetSymbolAddress((void**)&vn,     g_vn);
    cudaGetSymbolAddress((void**)&vt,     g_vt);
    cudaGetSymbolAddress((void**)&cf,     g_cf);

    const int SMEM128 = 3 * (128 * 80 + 128 * 80);        // 61440
    const int SMEMATT = 2 * 64 * 80 + 3 * (2 * 128 * 80); // 71680
    const int SMEMCTX = 3 * (2 * 64 * 80 + 2 * 64 * 80);  // 61440
    cudaFuncSetAttribute(mm_gemm,    cudaFuncAttributeMaxDynamicSharedMemorySize, SMEM128);
    cudaFuncSetAttribute(attn_fused, cudaFuncAttributeMaxDynamicSharedMemorySize, SMEMATT);
    cudaFuncSetAttribute(ctx_fused,  cudaFuncAttributeMaxDynamicSharedMemorySize, SMEMCTX);

    const int NXE = Mtot * Cn;

    // prep
    cvt16<<<(NXE / 4 + 255) / 256, 256>>>(x, xf, NXE / 4);
    tcvt<<<dim3(C3 / 32, Cn / 32), 256>>>(Wqkv, wqt, Cn, C3);
    tcvt<<<dim3(Cn / 32, Cn / 32), 256>>>(Wproj, wpt, Cn, Cn);

    // 1) QKV projection (fp16 1-term)
    mm_gemm<<<dim3(C3 / 128, 33, 1), 256, SMEM128>>>(0, xf, wqt,
        Mtot, C3, Cn, Cn, Cn, nullptr, nullptr, qf, kf, vn);

    // 2) fused scores (fp16, j-tile 128) + exp store + rowsum stats
    attn_fused<<<dim3(17, BH), 256, SMEMATT>>>(qf, kf, Eg, stats);

    // 2b) V transpose with padding (needed only by ctx)
    vtrans<<<dim3(DhD / 32, NPAD / 32, BH), 256>>>(vn, vt);

    // 2c) zero small buffers
    zero_misc<<<(Bn * Nn + 255) / 256, 256>>>(colsum, keep, cnt);

    // 3) column sums from E (half2 pairs)
    colsum3<<<dim3(3, Bn, Hh * 8), 256>>>(Eg, stats, colsum);

    // 4) UCB top-k
    topk_kernel<<<Bn, 1024>>>(colsum, ucb, cntr, uen, keep, cnt);

    // 5) masked renorm context from E -> cf fp16
    ctx_fused<<<dim3(17, BH), 256, SMEMCTX>>>(Eg, vt, stats, keep, cf);

    // 6) out projection (fp16 1-term)
    mm_gemm<<<dim3(6, 33, 1), 256, SMEM128>>>(3, cf, wpt,
        Mtot, Cn, Cn, Cn, Cn, (float*)d_out, bproj,
        nullptr, nullptr, nullptr);

    // 7) score_delta
    if (out_size >= Mtot * Cn + Hh * Nn) {
        float* out2 = (float*)d_out + (size_t)Mtot * Cn;
        score_delta_kernel<<<(Hh * Nn + 255) / 256, 256>>>(cnt, out2);
    }
}